// round 4
// baseline (speedup 1.0000x reference)
#include <cuda_runtime.h>

#define NN 100000
#define NE 3200000
#define NT (NE + NN)
#define NG 256

// ---------------- scratch (device globals; no allocation allowed) ----------------
__device__ float    g_xh[NN * 64];     // per-conv transformed node features
__device__ float    g_agg1[NN * 64];   // conv1 aggregation output
__device__ float    g_agg2[NN * 64];   // conv2 aggregation output
__device__ float    g_als[NN * 2];     // attention src logits (H<=2)
__device__ float    g_ald[NN * 2];     // attention dst logits
__device__ float    g_den[NN * 2];     // softmax denom, then reciprocal in-place
__device__ float    g_ex[NT * 2];      // per-edge unnormalized exp
__device__ float    g_bnsum[64];
__device__ float    g_bnsq[64];
__device__ float    g_scale[64];
__device__ float    g_shift[64];
__device__ float    g_psum[NG * 64];
__device__ unsigned g_pmax[NG * 64];
__device__ float    g_cnt[NG];

// ---------------- helpers ----------------
__device__ __forceinline__ float eluf(float x)  { return x > 0.f ? x : (__expf(x) - 1.f); }
__device__ __forceinline__ float lrelu(float x) { return x > 0.f ? x : 0.2f * x; }

// order-preserving float -> uint encoding for atomicMax
__device__ __forceinline__ unsigned fenc(float f) {
    unsigned u = __float_as_uint(f);
    return (u & 0x80000000u) ? ~u : (u | 0x80000000u);
}
__device__ __forceinline__ float fdec(unsigned e) {
    return (e & 0x80000000u) ? __uint_as_float(e ^ 0x80000000u) : __uint_as_float(~e);
}

__device__ __forceinline__ void red_v4(float* p, float a, float b, float c, float d) {
    asm volatile("red.global.add.v4.f32 [%0], {%1,%2,%3,%4};"
                 :: "l"(p), "f"(a), "f"(b), "f"(c), "f"(d) : "memory");
}
__device__ __forceinline__ void red_v2(float* p, float a, float b) {
    asm volatile("red.global.add.v2.f32 [%0], {%1,%2};"
                 :: "l"(p), "f"(a), "f"(b) : "memory");
}

// ---------------- zero kernels ----------------
__global__ void k_init() {
    int i = blockIdx.x * blockDim.x + threadIdx.x;
    int stride = gridDim.x * blockDim.x;
    for (int j = i; j < NN * 64; j += stride) { g_agg1[j] = 0.f; g_agg2[j] = 0.f; }
    for (int j = i; j < NN * 2; j += stride) g_den[j] = 0.f;
    for (int j = i; j < NG * 64; j += stride) { g_psum[j] = 0.f; g_pmax[j] = 0u; }
    if (i < NG) g_cnt[i] = 0.f;
    if (i < 64) { g_bnsum[i] = 0.f; g_bnsq[i] = 0.f; }
}

__global__ void k_zero_mid() {  // before conv2 edge passes
    int i = blockIdx.x * blockDim.x + threadIdx.x;
    int stride = gridDim.x * blockDim.x;
    for (int j = i; j < NN; j += stride) g_den[j] = 0.f;
    if (i < 64) { g_bnsum[i] = 0.f; g_bnsq[i] = 0.f; }
}

// ---------------- node kernels: fused input transform + 64x64 GEMM ----------------
// block = 256 threads, 32 nodes per block
__global__ __launch_bounds__(256) void k_node1(const float* __restrict__ x,
                                               const float* __restrict__ Wemb,
                                               const float* __restrict__ bemb,
                                               const float* __restrict__ W1, int nN) {
    __shared__ __align__(16) float sW[4096];
    __shared__ float sWe[256];
    __shared__ float sbe[64];
    __shared__ float sx[128];
    __shared__ float sh[2048];
    int tid = threadIdx.x;
    int n0 = blockIdx.x * 32;
    for (int i = tid; i < 4096; i += 256) sW[i] = W1[i];
    if (tid < 256) sWe[tid] = Wemb[tid];
    if (tid < 64) sbe[tid] = bemb[tid];
    if (tid < 128) {
        int n = tid >> 2, k = tid & 3;
        int node = n0 + n;
        sx[tid] = node < nN ? x[node * 4 + k] : 0.f;
    }
    __syncthreads();
    // embedding: h = elu(x @ Wemb + bemb)
    for (int i = tid; i < 2048; i += 256) {
        int n = i >> 6, c = i & 63;
        float acc = sbe[c];
#pragma unroll
        for (int k = 0; k < 4; k++) acc += sx[n * 4 + k] * sWe[k * 64 + c];
        sh[i] = eluf(acc);
    }
    __syncthreads();
    // GEMM: xh = h @ W1
    int w = tid >> 5, l = tid & 31;
    int c = l * 2;
    float acc[4][2] = {};
#pragma unroll 8
    for (int k = 0; k < 64; k++) {
        float2 wv = *(const float2*)&sW[k * 64 + c];
#pragma unroll
        for (int j = 0; j < 4; j++) {
            float hv = sh[(w + j * 8) * 64 + k];
            acc[j][0] += hv * wv.x;
            acc[j][1] += hv * wv.y;
        }
    }
#pragma unroll
    for (int j = 0; j < 4; j++) {
        int node = n0 + w + j * 8;
        if (node < nN) *(float2*)&g_xh[node * 64 + c] = make_float2(acc[j][0], acc[j][1]);
    }
}

__global__ __launch_bounds__(256) void k_node2(const float* __restrict__ W2, int nN) {
    __shared__ __align__(16) float sW[4096];
    __shared__ float ssc[64];
    __shared__ float ssh[64];
    __shared__ float sh[2048];
    int tid = threadIdx.x;
    int n0 = blockIdx.x * 32;
    for (int i = tid; i < 4096; i += 256) sW[i] = W2[i];
    if (tid < 64) { ssc[tid] = g_scale[tid]; ssh[tid] = g_shift[tid]; }
    __syncthreads();
    // input = elu(BN(agg1))
    for (int i = tid; i < 2048; i += 256) {
        int n = i >> 6, c = i & 63;
        int node = n0 + n;
        float v = node < nN ? g_agg1[node * 64 + c] : 0.f;
        sh[i] = eluf(ssc[c] * v + ssh[c]);
    }
    __syncthreads();
    int w = tid >> 5, l = tid & 31;
    int c = l * 2;
    float acc[4][2] = {};
#pragma unroll 8
    for (int k = 0; k < 64; k++) {
        float2 wv = *(const float2*)&sW[k * 64 + c];
#pragma unroll
        for (int j = 0; j < 4; j++) {
            float hv = sh[(w + j * 8) * 64 + k];
            acc[j][0] += hv * wv.x;
            acc[j][1] += hv * wv.y;
        }
    }
#pragma unroll
    for (int j = 0; j < 4; j++) {
        int node = n0 + w + j * 8;
        if (node < nN) *(float2*)&g_xh[node * 64 + c] = make_float2(acc[j][0], acc[j][1]);
    }
}

// ---------------- attention logits per node ----------------
__global__ void k_al2h(const float* __restrict__ a_src, const float* __restrict__ a_dst, int nN) {
    int node = (blockIdx.x * blockDim.x + threadIdx.x) >> 5;
    int lane = threadIdx.x & 31;
    if (node >= nN) return;
    float v0 = g_xh[node * 64 + lane];
    float v1 = g_xh[node * 64 + 32 + lane];
    float s0 = v0 * a_src[lane], s1 = v1 * a_src[32 + lane];
    float d0 = v0 * a_dst[lane], d1 = v1 * a_dst[32 + lane];
#pragma unroll
    for (int o = 16; o > 0; o >>= 1) {
        s0 += __shfl_down_sync(0xffffffffu, s0, o);
        s1 += __shfl_down_sync(0xffffffffu, s1, o);
        d0 += __shfl_down_sync(0xffffffffu, d0, o);
        d1 += __shfl_down_sync(0xffffffffu, d1, o);
    }
    if (lane == 0) {
        g_als[node * 2] = s0; g_als[node * 2 + 1] = s1;
        g_ald[node * 2] = d0; g_ald[node * 2 + 1] = d1;
    }
}

__global__ void k_al1h(const float* __restrict__ a_src, const float* __restrict__ a_dst, int nN) {
    int node = (blockIdx.x * blockDim.x + threadIdx.x) >> 5;
    int lane = threadIdx.x & 31;
    if (node >= nN) return;
    float v0 = g_xh[node * 64 + lane];
    float v1 = g_xh[node * 64 + 32 + lane];
    float s = v0 * a_src[lane] + v1 * a_src[32 + lane];
    float d = v0 * a_dst[lane] + v1 * a_dst[32 + lane];
#pragma unroll
    for (int o = 16; o > 0; o >>= 1) {
        s += __shfl_down_sync(0xffffffffu, s, o);
        d += __shfl_down_sync(0xffffffffu, d, o);
    }
    if (lane == 0) { g_als[node] = s; g_ald[node] = d; }
}

// ---------------- per-edge exp + denom ----------------
__global__ void k_ex2(const int* __restrict__ src, const int* __restrict__ dst, int E, int ET) {
    int e = blockIdx.x * blockDim.x + threadIdx.x;
    if (e >= ET) return;
    int s, d;
    if (e < E) { s = src[e]; d = dst[e]; } else { s = d = e - E; }
    float2 as = *(const float2*)&g_als[s * 2];
    float2 ad = *(const float2*)&g_ald[d * 2];
    float x0 = __expf(lrelu(as.x + ad.x));
    float x1 = __expf(lrelu(as.y + ad.y));
    *(float2*)&g_ex[e * 2] = make_float2(x0, x1);
    red_v2(&g_den[d * 2], x0, x1);
}

__global__ void k_ex1(const int* __restrict__ src, const int* __restrict__ dst, int E, int ET) {
    int e = blockIdx.x * blockDim.x + threadIdx.x;
    if (e >= ET) return;
    int s, d;
    if (e < E) { s = src[e]; d = dst[e]; } else { s = d = e - E; }
    float x0 = __expf(lrelu(g_als[s] + g_ald[d]));
    g_ex[e] = x0;
    atomicAdd(&g_den[d], x0);
}

__global__ void k_rdenom(int n) {
    int i = blockIdx.x * blockDim.x + threadIdx.x;
    if (i < n) g_den[i] = 1.f / (g_den[i] + 1e-16f);
}

// ---------------- edge aggregation: 16 threads/edge, v4 reductions ----------------
template <int CONV>
__global__ __launch_bounds__(256) void k_agg(const int* __restrict__ src,
                                             const int* __restrict__ dst, int E, int ET) {
    int t = blockIdx.x * 256 + threadIdx.x;
    int e = t >> 4;
    if (e >= ET) return;
    int l = t & 15;
    int s, d;
    if (e < E) { s = src[e]; d = dst[e]; } else { s = d = e - E; }
    constexpr int H = (CONV == 1) ? 2 : 1;
    int h = (CONV == 1) ? (l >> 3) : 0;
    float w = g_ex[e * H + h] * g_den[d * H + h];  // g_den holds 1/denom
    float4 v = *(const float4*)&g_xh[s * 64 + l * 4];
    float* agg = (CONV == 1) ? g_agg1 : g_agg2;
    red_v4(&agg[d * 64 + l * 4], v.x * w, v.y * w, v.z * w, v.w * w);
}

// ---------------- BatchNorm (training stats) ----------------
template <int CONV>
__global__ void k_bnstats(int nN) {
    const float* agg = (CONV == 1) ? g_agg1 : g_agg2;
    int t = blockIdx.x * blockDim.x + threadIdx.x;
    int c = t & 63;
    int r0 = t >> 6;
    int rs = (gridDim.x * blockDim.x) >> 6;
    float s = 0.f, q = 0.f;
    for (int n = r0; n < nN; n += rs) {
        float v = agg[n * 64 + c];
        s += v;
        q += v * v;
    }
    atomicAdd(&g_bnsum[c], s);
    atomicAdd(&g_bnsq[c], q);
}

__global__ void k_bnfin(const float* __restrict__ gamma, const float* __restrict__ beta, int nN) {
    int c = threadIdx.x;
    if (c >= 64) return;
    float inv = 1.f / (float)nN;
    float mu = g_bnsum[c] * inv;
    float var = g_bnsq[c] * inv - mu * mu;
    float rs = rsqrtf(fmaxf(var, 0.f) + 1e-5f);
    float sc = gamma[c] * rs;
    g_scale[c] = sc;
    g_shift[c] = beta[c] - mu * sc;
    // note: GAT bias b cancels exactly inside BN, never applied
}

// ---------------- pooling ----------------
__global__ void k_pool(const int* __restrict__ batch, int nN) {
    int t = blockIdx.x * blockDim.x + threadIdx.x;
    if (t >= nN * 64) return;
    int n = t >> 6, c = t & 63;
    int g = batch[n];
    float y = eluf(g_scale[c] * g_agg2[t] + g_shift[c]);
    atomicAdd(&g_psum[g * 64 + c], y);
    atomicMax(&g_pmax[g * 64 + c], fenc(y));
    if (c == 0) atomicAdd(&g_cnt[g], 1.f);
}

// ---------------- final projection ----------------
__global__ __launch_bounds__(128) void k_final(const float* __restrict__ Wout,
                                               const float* __restrict__ bout,
                                               float* __restrict__ out) {
    __shared__ float comb[128];
    int g = blockIdx.x, c = threadIdx.x;
    float cnt = g_cnt[g];
    if (c < 64) {
        comb[c] = (cnt > 0.f) ? fdec(g_pmax[g * 64 + c]) : 0.f;
    } else {
        comb[c] = g_psum[g * 64 + (c - 64)] / fmaxf(cnt, 1.f);
    }
    __syncthreads();
    float acc = bout[c];
#pragma unroll 16
    for (int k = 0; k < 128; k++) acc += comb[k] * Wout[k * 128 + c];
    out[g * 128 + c] = acc;
}

// ---------------- launcher ----------------
extern "C" void kernel_launch(void* const* d_in, const int* in_sizes, int n_in,
                              void* d_out, int out_size) {
    const float* x    = (const float*)d_in[0];
    const int*   ei   = (const int*)d_in[1];
    const int*   batch = (const int*)d_in[2];
    const float* Wemb = (const float*)d_in[3];
    const float* bemb = (const float*)d_in[4];
    const float* W1   = (const float*)d_in[5];
    const float* a1s  = (const float*)d_in[6];
    const float* a1d  = (const float*)d_in[7];
    // d_in[8] = b1 (cancels in BN)
    const float* g1   = (const float*)d_in[9];
    const float* be1  = (const float*)d_in[10];
    const float* W2   = (const float*)d_in[11];
    const float* a2s  = (const float*)d_in[12];
    const float* a2d  = (const float*)d_in[13];
    // d_in[14] = b2 (cancels in BN)
    const float* g2   = (const float*)d_in[15];
    const float* be2  = (const float*)d_in[16];
    const float* Wout = (const float*)d_in[17];
    const float* bout = (const float*)d_in[18];
    float* out = (float*)d_out;

    int nN = in_sizes[2];
    int E  = in_sizes[1] / 2;
    int ET = E + nN;
    const int* src = ei;
    const int* dst = ei + E;

    k_init<<<8192, 256>>>();

    // ---- conv1 (heads=2, out=32) ----
    k_node1<<<(nN + 31) / 32, 256>>>(x, Wemb, bemb, W1, nN);
    k_al2h<<<(nN * 32 + 255) / 256, 256>>>(a1s, a1d, nN);
    k_ex2<<<(ET + 255) / 256, 256>>>(src, dst, E, ET);
    k_rdenom<<<(nN * 2 + 255) / 256, 256>>>(nN * 2);
    k_agg<1><<<(ET * 16 + 255) / 256, 256>>>(src, dst, E, ET);
    k_bnstats<1><<<256, 256>>>(nN);
    k_bnfin<<<1, 64>>>(g1, be1, nN);
    k_zero_mid<<<512, 256>>>();

    // ---- conv2 (heads=1, out=64) ----
    k_node2<<<(nN + 31) / 32, 256>>>(W2, nN);
    k_al1h<<<(nN * 32 + 255) / 256, 256>>>(a2s, a2d, nN);
    k_ex1<<<(ET + 255) / 256, 256>>>(src, dst, E, ET);
    k_rdenom<<<(nN + 255) / 256, 256>>>(nN);
    k_agg<2><<<(ET * 16 + 255) / 256, 256>>>(src, dst, E, ET);
    k_bnstats<2><<<256, 256>>>(nN);
    k_bnfin<<<1, 64>>>(g2, be2, nN);

    // ---- pool + projection ----
    k_pool<<<(nN * 64 + 255) / 256, 256>>>(batch, nN);
    k_final<<<NG, 128>>>(Wout, bout, out);
}

// round 7
// speedup vs baseline: 1.5493x; 1.5493x over previous
#include <cuda_runtime.h>

#define NN 100000
#define NE 3200000
#define NG 256
#define SCAN_B 1024

// ---------------- scratch (device globals; no allocation allowed) ----------------
__device__ int      g_deg[NN];
__device__ int      g_rowptr[NN + 1];
__device__ int      g_cursor[NN];      // also scan temp (inclusive sums)
__device__ int      g_csr[NE];         // src node ids, grouped by dst
__device__ int      g_bsum[256];       // block sums for scan
__device__ float    g_xh[NN * 64];     // per-conv transformed node features
__device__ float    g_agg1[NN * 64];   // conv1 output (normalized, pre-BN)
__device__ float    g_agg2[NN * 64];   // conv2 output (normalized, pre-BN)
__device__ float    g_als[NN * 2];     // attention src logits (H<=2)
__device__ float    g_ald[NN * 2];     // attention dst logits
__device__ float    g_bnsum[64];
__device__ float    g_bnsq[64];
__device__ float    g_scale[64];
__device__ float    g_shift[64];
__device__ float    g_psum[NG * 64];
__device__ unsigned g_pmax[NG * 64];
__device__ float    g_cnt[NG];

// ---------------- helpers ----------------
__device__ __forceinline__ float eluf(float x)  { return x > 0.f ? x : (__expf(x) - 1.f); }
__device__ __forceinline__ float lrelu(float x) { return x > 0.f ? x : 0.2f * x; }

__device__ __forceinline__ unsigned fenc(float f) {
    unsigned u = __float_as_uint(f);
    return (u & 0x80000000u) ? ~u : (u | 0x80000000u);
}
__device__ __forceinline__ float fdec(unsigned e) {
    return (e & 0x80000000u) ? __uint_as_float(e ^ 0x80000000u) : __uint_as_float(~e);
}

// ---------------- zero / init ----------------
__global__ void k_init() {
    int i = blockIdx.x * blockDim.x + threadIdx.x;
    int stride = gridDim.x * blockDim.x;
    for (int j = i; j < NN; j += stride) g_deg[j] = 0;
    for (int j = i; j < NG * 64; j += stride) { g_psum[j] = 0.f; g_pmax[j] = 0u; }
    if (i < NG) g_cnt[i] = 0.f;
    if (i < 64) { g_bnsum[i] = 0.f; g_bnsq[i] = 0.f; }
}

__global__ void k_zero_bn() {
    int i = threadIdx.x;
    if (i < 64) { g_bnsum[i] = 0.f; g_bnsq[i] = 0.f; }
}

// ---------------- CSR build: histogram + scan + fill ----------------
__global__ void k_hist(const int* __restrict__ dst, int E) {
    int e = blockIdx.x * blockDim.x + threadIdx.x;
    if (e < E) atomicAdd(&g_deg[dst[e]], 1);
}

__global__ __launch_bounds__(SCAN_B) void k_scan_a(int n) {
    __shared__ int sh[SCAN_B];
    int tid = threadIdx.x;
    int i = blockIdx.x * SCAN_B + tid;
    int v = (i < n) ? g_deg[i] : 0;
    sh[tid] = v;
    __syncthreads();
    for (int o = 1; o < SCAN_B; o <<= 1) {
        int t = (tid >= o) ? sh[tid - o] : 0;
        __syncthreads();
        sh[tid] += t;
        __syncthreads();
    }
    if (i < n) g_cursor[i] = sh[tid];            // inclusive within block
    if (tid == SCAN_B - 1) g_bsum[blockIdx.x] = sh[tid];
}

__global__ __launch_bounds__(128) void k_scan_b(int nb) {
    __shared__ int sh[128];
    int tid = threadIdx.x;
    int v = (tid < nb) ? g_bsum[tid] : 0;
    sh[tid] = v;
    __syncthreads();
    for (int o = 1; o < 128; o <<= 1) {
        int t = (tid >= o) ? sh[tid - o] : 0;
        __syncthreads();
        sh[tid] += t;
        __syncthreads();
    }
    if (tid < nb) g_bsum[tid] = sh[tid] - v;     // exclusive block offsets
}

__global__ void k_scan_c(int n) {
    int i = blockIdx.x * blockDim.x + threadIdx.x;
    if (i >= n) return;
    int off = g_bsum[i / SCAN_B];
    int incl = g_cursor[i];
    int rp = off + incl - g_deg[i];              // exclusive prefix
    g_rowptr[i] = rp;
    g_cursor[i] = rp;
    if (i == n - 1) g_rowptr[n] = off + incl;
}

__global__ void k_fill(const int* __restrict__ src, const int* __restrict__ dst, int E) {
    int e = blockIdx.x * blockDim.x + threadIdx.x;
    if (e >= E) return;
    int d = dst[e];
    int pos = atomicAdd(&g_cursor[d], 1);
    g_csr[pos] = src[e];
}

// ---------------- node kernels: fused input transform + 64x64 GEMM ----------------
__global__ __launch_bounds__(256) void k_node1(const float* __restrict__ x,
                                               const float* __restrict__ Wemb,
                                               const float* __restrict__ bemb,
                                               const float* __restrict__ W1, int nN) {
    __shared__ __align__(16) float sW[4096];
    __shared__ float sWe[256];
    __shared__ float sbe[64];
    __shared__ float sx[128];
    __shared__ float sh[2048];
    int tid = threadIdx.x;
    int n0 = blockIdx.x * 32;
    for (int i = tid; i < 4096; i += 256) sW[i] = W1[i];
    if (tid < 256) sWe[tid] = Wemb[tid];
    if (tid < 64) sbe[tid] = bemb[tid];
    if (tid < 128) {
        int n = tid >> 2, k = tid & 3;
        int node = n0 + n;
        sx[tid] = node < nN ? x[node * 4 + k] : 0.f;
    }
    __syncthreads();
    for (int i = tid; i < 2048; i += 256) {
        int n = i >> 6, c = i & 63;
        float acc = sbe[c];
#pragma unroll
        for (int k = 0; k < 4; k++) acc += sx[n * 4 + k] * sWe[k * 64 + c];
        sh[i] = eluf(acc);
    }
    __syncthreads();
    int w = tid >> 5, l = tid & 31;
    int c = l * 2;
    float acc[4][2] = {};
#pragma unroll 8
    for (int k = 0; k < 64; k++) {
        float2 wv = *(const float2*)&sW[k * 64 + c];
#pragma unroll
        for (int j = 0; j < 4; j++) {
            float hv = sh[(w + j * 8) * 64 + k];
            acc[j][0] += hv * wv.x;
            acc[j][1] += hv * wv.y;
        }
    }
#pragma unroll
    for (int j = 0; j < 4; j++) {
        int node = n0 + w + j * 8;
        if (node < nN) *(float2*)&g_xh[node * 64 + c] = make_float2(acc[j][0], acc[j][1]);
    }
}

__global__ __launch_bounds__(256) void k_node2(const float* __restrict__ W2, int nN) {
    __shared__ __align__(16) float sW[4096];
    __shared__ float ssc[64];
    __shared__ float ssh[64];
    __shared__ float sh[2048];
    int tid = threadIdx.x;
    int n0 = blockIdx.x * 32;
    for (int i = tid; i < 4096; i += 256) sW[i] = W2[i];
    if (tid < 64) { ssc[tid] = g_scale[tid]; ssh[tid] = g_shift[tid]; }
    __syncthreads();
    for (int i = tid; i < 2048; i += 256) {
        int n = i >> 6, c = i & 63;
        int node = n0 + n;
        float v = node < nN ? g_agg1[node * 64 + c] : 0.f;
        sh[i] = eluf(ssc[c] * v + ssh[c]);
    }
    __syncthreads();
    int w = tid >> 5, l = tid & 31;
    int c = l * 2;
    float acc[4][2] = {};
#pragma unroll 8
    for (int k = 0; k < 64; k++) {
        float2 wv = *(const float2*)&sW[k * 64 + c];
#pragma unroll
        for (int j = 0; j < 4; j++) {
            float hv = sh[(w + j * 8) * 64 + k];
            acc[j][0] += hv * wv.x;
            acc[j][1] += hv * wv.y;
        }
    }
#pragma unroll
    for (int j = 0; j < 4; j++) {
        int node = n0 + w + j * 8;
        if (node < nN) *(float2*)&g_xh[node * 64 + c] = make_float2(acc[j][0], acc[j][1]);
    }
}

// ---------------- attention logits per node ----------------
__global__ void k_al2h(const float* __restrict__ a_src, const float* __restrict__ a_dst, int nN) {
    int node = (blockIdx.x * blockDim.x + threadIdx.x) >> 5;
    int lane = threadIdx.x & 31;
    if (node >= nN) return;
    float v0 = g_xh[node * 64 + lane];
    float v1 = g_xh[node * 64 + 32 + lane];
    float s0 = v0 * a_src[lane], s1 = v1 * a_src[32 + lane];
    float d0 = v0 * a_dst[lane], d1 = v1 * a_dst[32 + lane];
#pragma unroll
    for (int o = 16; o > 0; o >>= 1) {
        s0 += __shfl_down_sync(0xffffffffu, s0, o);
        s1 += __shfl_down_sync(0xffffffffu, s1, o);
        d0 += __shfl_down_sync(0xffffffffu, d0, o);
        d1 += __shfl_down_sync(0xffffffffu, d1, o);
    }
    if (lane == 0) {
        g_als[node * 2] = s0; g_als[node * 2 + 1] = s1;
        g_ald[node * 2] = d0; g_ald[node * 2 + 1] = d1;
    }
}

__global__ void k_al1h(const float* __restrict__ a_src, const float* __restrict__ a_dst, int nN) {
    int node = (blockIdx.x * blockDim.x + threadIdx.x) >> 5;
    int lane = threadIdx.x & 31;
    if (node >= nN) return;
    float v0 = g_xh[node * 64 + lane];
    float v1 = g_xh[node * 64 + 32 + lane];
    float s = v0 * a_src[lane] + v1 * a_src[32 + lane];
    float d = v0 * a_dst[lane] + v1 * a_dst[32 + lane];
#pragma unroll
    for (int o = 16; o > 0; o >>= 1) {
        s += __shfl_down_sync(0xffffffffu, s, o);
        d += __shfl_down_sync(0xffffffffu, d, o);
    }
    if (lane == 0) { g_als[node] = s; g_ald[node] = d; }
}

// ---------------- GAT aggregation: one warp per dst node over CSR ----------------
// conv1: heads=2 (channels 0-31 head0, 32-63 head1); lane handles channels 2l, 2l+1
__global__ __launch_bounds__(256) void k_gat1(int nN) {
    int d = (blockIdx.x * 256 + threadIdx.x) >> 5;
    if (d >= nN) return;
    int lane = threadIdx.x & 31;
    int c2 = lane * 2;
    int beg = g_rowptr[d], end = g_rowptr[d + 1];
    float2 aldd = *(const float2*)&g_ald[d * 2];
    float acc0 = 0.f, acc1 = 0.f, dn0 = 0.f, dn1 = 0.f;
    for (int base = beg; base < end; base += 32) {
        int cnt = min(32, end - base);
        int si = 0; float ex0 = 0.f, ex1 = 0.f;
        if (lane < cnt) {
            si = g_csr[base + lane];
            float2 as = *(const float2*)&g_als[si * 2];
            ex0 = __expf(lrelu(as.x + aldd.x));
            ex1 = __expf(lrelu(as.y + aldd.y));
        }
        dn0 += ex0; dn1 += ex1;
        int j = 0;
        for (; j + 4 <= cnt; j += 4) {
            int s0 = __shfl_sync(0xffffffffu, si, j);
            int s1 = __shfl_sync(0xffffffffu, si, j + 1);
            int s2 = __shfl_sync(0xffffffffu, si, j + 2);
            int s3 = __shfl_sync(0xffffffffu, si, j + 3);
            float a0 = __shfl_sync(0xffffffffu, ex0, j),     b0 = __shfl_sync(0xffffffffu, ex1, j);
            float a1 = __shfl_sync(0xffffffffu, ex0, j + 1), b1 = __shfl_sync(0xffffffffu, ex1, j + 1);
            float a2 = __shfl_sync(0xffffffffu, ex0, j + 2), b2 = __shfl_sync(0xffffffffu, ex1, j + 2);
            float a3 = __shfl_sync(0xffffffffu, ex0, j + 3), b3 = __shfl_sync(0xffffffffu, ex1, j + 3);
            float2 v0 = *(const float2*)&g_xh[s0 * 64 + c2];
            float2 v1 = *(const float2*)&g_xh[s1 * 64 + c2];
            float2 v2 = *(const float2*)&g_xh[s2 * 64 + c2];
            float2 v3 = *(const float2*)&g_xh[s3 * 64 + c2];
            float w0 = lane < 16 ? a0 : b0;
            float w1 = lane < 16 ? a1 : b1;
            float w2 = lane < 16 ? a2 : b2;
            float w3 = lane < 16 ? a3 : b3;
            acc0 += w0 * v0.x; acc1 += w0 * v0.y;
            acc0 += w1 * v1.x; acc1 += w1 * v1.y;
            acc0 += w2 * v2.x; acc1 += w2 * v2.y;
            acc0 += w3 * v3.x; acc1 += w3 * v3.y;
        }
        for (; j < cnt; j++) {
            int s0 = __shfl_sync(0xffffffffu, si, j);
            float a0 = __shfl_sync(0xffffffffu, ex0, j), b0 = __shfl_sync(0xffffffffu, ex1, j);
            float w0 = lane < 16 ? a0 : b0;
            float2 v0 = *(const float2*)&g_xh[s0 * 64 + c2];
            acc0 += w0 * v0.x; acc1 += w0 * v0.y;
        }
    }
    // self loop
    {
        float2 as = *(const float2*)&g_als[d * 2];
        float ex0 = __expf(lrelu(as.x + aldd.x));
        float ex1 = __expf(lrelu(as.y + aldd.y));
        if (lane == 0) { dn0 += ex0; dn1 += ex1; }
        float w = lane < 16 ? ex0 : ex1;
        float2 v = *(const float2*)&g_xh[d * 64 + c2];
        acc0 += w * v.x; acc1 += w * v.y;
    }
#pragma unroll
    for (int o = 16; o > 0; o >>= 1) {
        dn0 += __shfl_xor_sync(0xffffffffu, dn0, o);
        dn1 += __shfl_xor_sync(0xffffffffu, dn1, o);
    }
    float rd = 1.f / (((lane < 16) ? dn0 : dn1) + 1e-16f);
    *(float2*)&g_agg1[d * 64 + c2] = make_float2(acc0 * rd, acc1 * rd);
}

// conv2: heads=1, 64 channels
__global__ __launch_bounds__(256) void k_gat2(int nN) {
    int d = (blockIdx.x * 256 + threadIdx.x) >> 5;
    if (d >= nN) return;
    int lane = threadIdx.x & 31;
    int c2 = lane * 2;
    int beg = g_rowptr[d], end = g_rowptr[d + 1];
    float aldd = g_ald[d];
    float acc0 = 0.f, acc1 = 0.f, dn = 0.f;
    for (int base = beg; base < end; base += 32) {
        int cnt = min(32, end - base);
        int si = 0; float ex = 0.f;
        if (lane < cnt) {
            si = g_csr[base + lane];
            ex = __expf(lrelu(g_als[si] + aldd));
        }
        dn += ex;
        int j = 0;
        for (; j + 4 <= cnt; j += 4) {
            int s0 = __shfl_sync(0xffffffffu, si, j);
            int s1 = __shfl_sync(0xffffffffu, si, j + 1);
            int s2 = __shfl_sync(0xffffffffu, si, j + 2);
            int s3 = __shfl_sync(0xffffffffu, si, j + 3);
            float w0 = __shfl_sync(0xffffffffu, ex, j);
            float w1 = __shfl_sync(0xffffffffu, ex, j + 1);
            float w2 = __shfl_sync(0xffffffffu, ex, j + 2);
            float w3 = __shfl_sync(0xffffffffu, ex, j + 3);
            float2 v0 = *(const float2*)&g_xh[s0 * 64 + c2];
            float2 v1 = *(const float2*)&g_xh[s1 * 64 + c2];
            float2 v2 = *(const float2*)&g_xh[s2 * 64 + c2];
            float2 v3 = *(const float2*)&g_xh[s3 * 64 + c2];
            acc0 += w0 * v0.x; acc1 += w0 * v0.y;
            acc0 += w1 * v1.x; acc1 += w1 * v1.y;
            acc0 += w2 * v2.x; acc1 += w2 * v2.y;
            acc0 += w3 * v3.x; acc1 += w3 * v3.y;
        }
        for (; j < cnt; j++) {
            int s0 = __shfl_sync(0xffffffffu, si, j);
            float w0 = __shfl_sync(0xffffffffu, ex, j);
            float2 v0 = *(const float2*)&g_xh[s0 * 64 + c2];
            acc0 += w0 * v0.x; acc1 += w0 * v0.y;
        }
    }
    {
        float ex = __expf(lrelu(g_als[d] + aldd));
        if (lane == 0) dn += ex;
        float2 v = *(const float2*)&g_xh[d * 64 + c2];
        acc0 += ex * v.x; acc1 += ex * v.y;
    }
#pragma unroll
    for (int o = 16; o > 0; o >>= 1) dn += __shfl_xor_sync(0xffffffffu, dn, o);
    float rd = 1.f / (dn + 1e-16f);
    *(float2*)&g_agg2[d * 64 + c2] = make_float2(acc0 * rd, acc1 * rd);
}

// ---------------- BatchNorm (training stats) ----------------
template <int CONV>
__global__ void k_bnstats(int nN) {
    const float* agg = (CONV == 1) ? g_agg1 : g_agg2;
    int t = blockIdx.x * blockDim.x + threadIdx.x;
    int c = t & 63;
    int r0 = t >> 6;
    int rs = (gridDim.x * blockDim.x) >> 6;
    float s = 0.f, q = 0.f;
    for (int n = r0; n < nN; n += rs) {
        float v = agg[n * 64 + c];
        s += v;
        q += v * v;
    }
    atomicAdd(&g_bnsum[c], s);
    atomicAdd(&g_bnsq[c], q);
}

__global__ void k_bnfin(const float* __restrict__ gamma, const float* __restrict__ beta, int nN) {
    int c = threadIdx.x;
    if (c >= 64) return;
    float inv = 1.f / (float)nN;
    float mu = g_bnsum[c] * inv;
    float var = g_bnsq[c] * inv - mu * mu;
    float rs = rsqrtf(fmaxf(var, 0.f) + 1e-5f);
    float sc = gamma[c] * rs;
    g_scale[c] = sc;
    g_shift[c] = beta[c] - mu * sc;
    // GAT bias b cancels exactly inside BN, never applied
}

// ---------------- pooling ----------------
__global__ void k_pool(const int* __restrict__ batch, int nN) {
    int t = blockIdx.x * blockDim.x + threadIdx.x;
    if (t >= nN * 64) return;
    int n = t >> 6, c = t & 63;
    int g = batch[n];
    float y = eluf(g_scale[c] * g_agg2[t] + g_shift[c]);
    atomicAdd(&g_psum[g * 64 + c], y);
    atomicMax(&g_pmax[g * 64 + c], fenc(y));
    if (c == 0) atomicAdd(&g_cnt[g], 1.f);
}

// ---------------- final projection ----------------
__global__ __launch_bounds__(128) void k_final(const float* __restrict__ Wout,
                                               const float* __restrict__ bout,
                                               float* __restrict__ out) {
    __shared__ float comb[128];
    int g = blockIdx.x, c = threadIdx.x;
    float cnt = g_cnt[g];
    if (c < 64) {
        comb[c] = (cnt > 0.f) ? fdec(g_pmax[g * 64 + c]) : 0.f;
    } else {
        comb[c] = g_psum[g * 64 + (c - 64)] / fmaxf(cnt, 1.f);
    }
    __syncthreads();
    float acc = bout[c];
#pragma unroll 16
    for (int k = 0; k < 128; k++) acc += comb[k] * Wout[k * 128 + c];
    out[g * 128 + c] = acc;
}

// ---------------- launcher ----------------
extern "C" void kernel_launch(void* const* d_in, const int* in_sizes, int n_in,
                              void* d_out, int out_size) {
    const float* x     = (const float*)d_in[0];
    const int*   ei    = (const int*)d_in[1];
    const int*   batch = (const int*)d_in[2];
    const float* Wemb  = (const float*)d_in[3];
    const float* bemb  = (const float*)d_in[4];
    const float* W1    = (const float*)d_in[5];
    const float* a1s   = (const float*)d_in[6];
    const float* a1d   = (const float*)d_in[7];
    // d_in[8] = b1 (cancels in BN)
    const float* g1    = (const float*)d_in[9];
    const float* be1   = (const float*)d_in[10];
    const float* W2    = (const float*)d_in[11];
    const float* a2s   = (const float*)d_in[12];
    const float* a2d   = (const float*)d_in[13];
    // d_in[14] = b2 (cancels in BN)
    const float* g2    = (const float*)d_in[15];
    const float* be2   = (const float*)d_in[16];
    const float* Wout  = (const float*)d_in[17];
    const float* bout  = (const float*)d_in[18];
    float* out = (float*)d_out;

    int nN = in_sizes[2];
    int E  = in_sizes[1] / 2;
    const int* src = ei;
    const int* dst = ei + E;

    k_init<<<1024, 256>>>();

    // ---- CSR by dst (built once, shared by both convs) ----
    k_hist<<<(E + 255) / 256, 256>>>(dst, E);
    int nb = (nN + SCAN_B - 1) / SCAN_B;
    k_scan_a<<<nb, SCAN_B>>>(nN);
    k_scan_b<<<1, 128>>>(nb);
    k_scan_c<<<(nN + 255) / 256, 256>>>(nN);
    k_fill<<<(E + 255) / 256, 256>>>(src, dst, E);

    // ---- conv1 (heads=2, out=32) ----
    k_node1<<<(nN + 31) / 32, 256>>>(x, Wemb, bemb, W1, nN);
    k_al2h<<<(nN * 32 + 255) / 256, 256>>>(a1s, a1d, nN);
    k_gat1<<<(nN * 32 + 255) / 256, 256>>>(nN);
    k_bnstats<1><<<256, 256>>>(nN);
    k_bnfin<<<1, 64>>>(g1, be1, nN);
    k_zero_bn<<<1, 64>>>();

    // ---- conv2 (heads=1, out=64) ----
    k_node2<<<(nN + 31) / 32, 256>>>(W2, nN);
    k_al1h<<<(nN * 32 + 255) / 256, 256>>>(a2s, a2d, nN);
    k_gat2<<<(nN * 32 + 255) / 256, 256>>>(nN);
    k_bnstats<2><<<256, 256>>>(nN);
    k_bnfin<<<1, 64>>>(g2, be2, nN);

    // ---- pool + projection ----
    k_pool<<<(nN * 64 + 255) / 256, 256>>>(batch, nN);
    k_final<<<NG, 128>>>(Wout, bout, out);
}

// round 13
// speedup vs baseline: 1.5511x; 1.0012x over previous
#include <cuda_runtime.h>

#define NN 100000
#define NE 3200000
#define NG 256
#define SCAN_B 1024

// ---------------- scratch (device globals; no allocation allowed) ----------------
__device__ int      g_deg[NN];
__device__ int      g_rowptr[NN + 1];
__device__ int      g_cursor[NN];      // also scan temp (inclusive sums)
__device__ int      g_csr[NE];         // src node ids, grouped by dst
__device__ int      g_bsum[256];       // block sums for scan
__device__ float    g_xh[NN * 64];     // per-conv transformed node features
__device__ float    g_agg1[NN * 64];   // conv1 output (normalized, pre-BN)
__device__ float    g_agg2[NN * 64];   // conv2 output (normalized, pre-BN)
__device__ float    g_als[NN * 2];     // attention src logits (H<=2)
__device__ float    g_ald[NN * 2];     // attention dst logits
__device__ float    g_bnsum[64];
__device__ float    g_bnsq[64];
__device__ float    g_scale[64];
__device__ float    g_shift[64];
__device__ float    g_psum[NG * 64];
__device__ unsigned g_pmax[NG * 64];
__device__ float    g_cnt[NG];

// ---------------- helpers ----------------
__device__ __forceinline__ float eluf(float x)  { return x > 0.f ? x : (__expf(x) - 1.f); }
__device__ __forceinline__ float lrelu(float x) { return x > 0.f ? x : 0.2f * x; }

__device__ __forceinline__ unsigned fenc(float f) {
    unsigned u = __float_as_uint(f);
    return (u & 0x80000000u) ? ~u : (u | 0x80000000u);
}
__device__ __forceinline__ float fdec(unsigned e) {
    return (e & 0x80000000u) ? __uint_as_float(e ^ 0x80000000u) : __uint_as_float(~e);
}

// ---------------- zero / init ----------------
__global__ void k_init() {
    int i = blockIdx.x * blockDim.x + threadIdx.x;
    int stride = gridDim.x * blockDim.x;
    for (int j = i; j < NN; j += stride) g_deg[j] = 0;
    for (int j = i; j < NG * 64; j += stride) { g_psum[j] = 0.f; g_pmax[j] = 0u; }
    if (i < NG) g_cnt[i] = 0.f;
    if (i < 64) { g_bnsum[i] = 0.f; g_bnsq[i] = 0.f; }
}

// ---------------- CSR build: histogram + scan + fill ----------------
__global__ void k_hist(const int* __restrict__ dst, int E) {
    int e = blockIdx.x * blockDim.x + threadIdx.x;
    if (e < E) atomicAdd(&g_deg[dst[e]], 1);
}

__global__ __launch_bounds__(SCAN_B) void k_scan_a(int n) {
    __shared__ int sh[SCAN_B];
    int tid = threadIdx.x;
    int i = blockIdx.x * SCAN_B + tid;
    int v = (i < n) ? g_deg[i] : 0;
    sh[tid] = v;
    __syncthreads();
    for (int o = 1; o < SCAN_B; o <<= 1) {
        int t = (tid >= o) ? sh[tid - o] : 0;
        __syncthreads();
        sh[tid] += t;
        __syncthreads();
    }
    if (i < n) g_cursor[i] = sh[tid];            // inclusive within block
    if (tid == SCAN_B - 1) g_bsum[blockIdx.x] = sh[tid];
}

__global__ __launch_bounds__(128) void k_scan_b(int nb) {
    __shared__ int sh[128];
    int tid = threadIdx.x;
    int v = (tid < nb) ? g_bsum[tid] : 0;
    sh[tid] = v;
    __syncthreads();
    for (int o = 1; o < 128; o <<= 1) {
        int t = (tid >= o) ? sh[tid - o] : 0;
        __syncthreads();
        sh[tid] += t;
        __syncthreads();
    }
    if (tid < nb) g_bsum[tid] = sh[tid] - v;     // exclusive block offsets
}

__global__ void k_scan_c(int n) {
    int i = blockIdx.x * blockDim.x + threadIdx.x;
    if (i >= n) return;
    int off = g_bsum[i / SCAN_B];
    int incl = g_cursor[i];
    int rp = off + incl - g_deg[i];              // exclusive prefix
    g_rowptr[i] = rp;
    g_cursor[i] = rp;
    if (i == n - 1) g_rowptr[n] = off + incl;
}

__global__ void k_fill(const int* __restrict__ src, const int* __restrict__ dst, int E) {
    int e = blockIdx.x * blockDim.x + threadIdx.x;
    if (e >= E) return;
    int d = dst[e];
    int pos = atomicAdd(&g_cursor[d], 1);
    g_csr[pos] = src[e];
}

// ---------------- node kernels: fused transform + 64x64 GEMM + attention logits ----------------
// block = 256 threads, 32 nodes per block; warp w owns nodes n0+w+{0,8,16,24}
__global__ __launch_bounds__(256) void k_node1(const float* __restrict__ x,
                                               const float* __restrict__ Wemb,
                                               const float* __restrict__ bemb,
                                               const float* __restrict__ W1,
                                               const float* __restrict__ a1s,
                                               const float* __restrict__ a1d, int nN) {
    __shared__ __align__(16) float sW[4096];
    __shared__ float sWe[256];
    __shared__ float sbe[64];
    __shared__ float sx[128];
    __shared__ float sh[2048];
    int tid = threadIdx.x;
    int n0 = blockIdx.x * 32;
    for (int i = tid; i < 4096; i += 256) sW[i] = W1[i];
    if (tid < 256) sWe[tid] = Wemb[tid];
    if (tid < 64) sbe[tid] = bemb[tid];
    if (tid < 128) {
        int n = tid >> 2, k = tid & 3;
        int node = n0 + n;
        sx[tid] = node < nN ? x[node * 4 + k] : 0.f;
    }
    __syncthreads();
    for (int i = tid; i < 2048; i += 256) {
        int n = i >> 6, c = i & 63;
        float acc = sbe[c];
#pragma unroll
        for (int k = 0; k < 4; k++) acc += sx[n * 4 + k] * sWe[k * 64 + c];
        sh[i] = eluf(acc);
    }
    __syncthreads();
    int w = tid >> 5, l = tid & 31;
    int c = l * 2;
    float2 avs = *(const float2*)&a1s[c];
    float2 avd = *(const float2*)&a1d[c];
    float acc[4][2] = {};
#pragma unroll 8
    for (int k = 0; k < 64; k++) {
        float2 wv = *(const float2*)&sW[k * 64 + c];
#pragma unroll
        for (int j = 0; j < 4; j++) {
            float hv = sh[(w + j * 8) * 64 + k];
            acc[j][0] += hv * wv.x;
            acc[j][1] += hv * wv.y;
        }
    }
#pragma unroll
    for (int j = 0; j < 4; j++) {
        int node = n0 + w + j * 8;
        if (node < nN) *(float2*)&g_xh[node * 64 + c] = make_float2(acc[j][0], acc[j][1]);
        // attention logits: head0 = channels 0-31 (lanes 0-15), head1 = 32-63 (lanes 16-31)
        float ps = avs.x * acc[j][0] + avs.y * acc[j][1];
        float pd = avd.x * acc[j][0] + avd.y * acc[j][1];
#pragma unroll
        for (int o = 1; o < 16; o <<= 1) {
            ps += __shfl_xor_sync(0xffffffffu, ps, o);
            pd += __shfl_xor_sync(0xffffffffu, pd, o);
        }
        if (node < nN) {
            if (l == 0)  { g_als[node * 2]     = ps; g_ald[node * 2]     = pd; }
            if (l == 16) { g_als[node * 2 + 1] = ps; g_ald[node * 2 + 1] = pd; }
        }
    }
}

__global__ __launch_bounds__(256) void k_node2(const float* __restrict__ W2,
                                               const float* __restrict__ a2s,
                                               const float* __restrict__ a2d, int nN) {
    __shared__ __align__(16) float sW[4096];
    __shared__ float ssc[64];
    __shared__ float ssh[64];
    __shared__ float sh[2048];
    int tid = threadIdx.x;
    int n0 = blockIdx.x * 32;
    for (int i = tid; i < 4096; i += 256) sW[i] = W2[i];
    if (tid < 64) { ssc[tid] = g_scale[tid]; ssh[tid] = g_shift[tid]; }
    __syncthreads();
    for (int i = tid; i < 2048; i += 256) {
        int n = i >> 6, c = i & 63;
        int node = n0 + n;
        float v = node < nN ? g_agg1[node * 64 + c] : 0.f;
        sh[i] = eluf(ssc[c] * v + ssh[c]);
    }
    __syncthreads();
    int w = tid >> 5, l = tid & 31;
    int c = l * 2;
    float2 avs = *(const float2*)&a2s[c];
    float2 avd = *(const float2*)&a2d[c];
    float acc[4][2] = {};
#pragma unroll 8
    for (int k = 0; k < 64; k++) {
        float2 wv = *(const float2*)&sW[k * 64 + c];
#pragma unroll
        for (int j = 0; j < 4; j++) {
            float hv = sh[(w + j * 8) * 64 + k];
            acc[j][0] += hv * wv.x;
            acc[j][1] += hv * wv.y;
        }
    }
#pragma unroll
    for (int j = 0; j < 4; j++) {
        int node = n0 + w + j * 8;
        if (node < nN) *(float2*)&g_xh[node * 64 + c] = make_float2(acc[j][0], acc[j][1]);
        float ps = avs.x * acc[j][0] + avs.y * acc[j][1];
        float pd = avd.x * acc[j][0] + avd.y * acc[j][1];
#pragma unroll
        for (int o = 1; o < 32; o <<= 1) {
            ps += __shfl_xor_sync(0xffffffffu, ps, o);
            pd += __shfl_xor_sync(0xffffffffu, pd, o);
        }
        if (node < nN && l == 0) { g_als[node] = ps; g_ald[node] = pd; }
    }
}

// ---------------- GAT aggregation: one warp per dst node over CSR, fused BN stats ----------------
// conv1: heads=2 (channels 0-31 head0, 32-63 head1); lane handles channels 2l, 2l+1
__global__ __launch_bounds__(256) void k_gat1(int nN) {
    __shared__ float ssum[64];
    __shared__ float ssq[64];
    int tid = threadIdx.x;
    if (tid < 64) { ssum[tid] = 0.f; ssq[tid] = 0.f; }
    __syncthreads();
    int d = (blockIdx.x * 256 + tid) >> 5;
    int lane = tid & 31;
    int c2 = lane * 2;
    if (d < nN) {
        int beg = g_rowptr[d], end = g_rowptr[d + 1];
        float2 aldd = *(const float2*)&g_ald[d * 2];
        float acc0 = 0.f, acc1 = 0.f, dn0 = 0.f, dn1 = 0.f;
        for (int base = beg; base < end; base += 32) {
            int cnt = min(32, end - base);
            int si = 0; float ex0 = 0.f, ex1 = 0.f;
            if (lane < cnt) {
                si = g_csr[base + lane];
                float2 as = *(const float2*)&g_als[si * 2];
                ex0 = __expf(lrelu(as.x + aldd.x));
                ex1 = __expf(lrelu(as.y + aldd.y));
            }
            dn0 += ex0; dn1 += ex1;
            int j = 0;
            for (; j + 4 <= cnt; j += 4) {
                int s0 = __shfl_sync(0xffffffffu, si, j);
                int s1 = __shfl_sync(0xffffffffu, si, j + 1);
                int s2 = __shfl_sync(0xffffffffu, si, j + 2);
                int s3 = __shfl_sync(0xffffffffu, si, j + 3);
                float a0 = __shfl_sync(0xffffffffu, ex0, j),     b0 = __shfl_sync(0xffffffffu, ex1, j);
                float a1 = __shfl_sync(0xffffffffu, ex0, j + 1), b1 = __shfl_sync(0xffffffffu, ex1, j + 1);
                float a2 = __shfl_sync(0xffffffffu, ex0, j + 2), b2 = __shfl_sync(0xffffffffu, ex1, j + 2);
                float a3 = __shfl_sync(0xffffffffu, ex0, j + 3), b3 = __shfl_sync(0xffffffffu, ex1, j + 3);
                float2 v0 = *(const float2*)&g_xh[s0 * 64 + c2];
                float2 v1 = *(const float2*)&g_xh[s1 * 64 + c2];
                float2 v2 = *(const float2*)&g_xh[s2 * 64 + c2];
                float2 v3 = *(const float2*)&g_xh[s3 * 64 + c2];
                float w0 = lane < 16 ? a0 : b0;
                float w1 = lane < 16 ? a1 : b1;
                float w2 = lane < 16 ? a2 : b2;
                float w3 = lane < 16 ? a3 : b3;
                acc0 += w0 * v0.x; acc1 += w0 * v0.y;
                acc0 += w1 * v1.x; acc1 += w1 * v1.y;
                acc0 += w2 * v2.x; acc1 += w2 * v2.y;
                acc0 += w3 * v3.x; acc1 += w3 * v3.y;
            }
            for (; j < cnt; j++) {
                int s0 = __shfl_sync(0xffffffffu, si, j);
                float a0 = __shfl_sync(0xffffffffu, ex0, j), b0 = __shfl_sync(0xffffffffu, ex1, j);
                float w0 = lane < 16 ? a0 : b0;
                float2 v0 = *(const float2*)&g_xh[s0 * 64 + c2];
                acc0 += w0 * v0.x; acc1 += w0 * v0.y;
            }
        }
        // self loop
        {
            float2 as = *(const float2*)&g_als[d * 2];
            float ex0 = __expf(lrelu(as.x + aldd.x));
            float ex1 = __expf(lrelu(as.y + aldd.y));
            if (lane == 0) { dn0 += ex0; dn1 += ex1; }
            float w = lane < 16 ? ex0 : ex1;
            float2 v = *(const float2*)&g_xh[d * 64 + c2];
            acc0 += w * v.x; acc1 += w * v.y;
        }
#pragma unroll
        for (int o = 16; o > 0; o >>= 1) {
            dn0 += __shfl_xor_sync(0xffffffffu, dn0, o);
            dn1 += __shfl_xor_sync(0xffffffffu, dn1, o);
        }
        float rd = 1.f / (((lane < 16) ? dn0 : dn1) + 1e-16f);
        float o0 = acc0 * rd, o1 = acc1 * rd;
        *(float2*)&g_agg1[d * 64 + c2] = make_float2(o0, o1);
        atomicAdd(&ssum[c2], o0);     atomicAdd(&ssum[c2 + 1], o1);
        atomicAdd(&ssq[c2], o0 * o0); atomicAdd(&ssq[c2 + 1], o1 * o1);
    }
    __syncthreads();
    if (tid < 64) {
        atomicAdd(&g_bnsum[tid], ssum[tid]);
        atomicAdd(&g_bnsq[tid], ssq[tid]);
    }
}

// conv2: heads=1, 64 channels
__global__ __launch_bounds__(256) void k_gat2(int nN) {
    __shared__ float ssum[64];
    __shared__ float ssq[64];
    int tid = threadIdx.x;
    if (tid < 64) { ssum[tid] = 0.f; ssq[tid] = 0.f; }
    __syncthreads();
    int d = (blockIdx.x * 256 + tid) >> 5;
    int lane = tid & 31;
    int c2 = lane * 2;
    if (d < nN) {
        int beg = g_rowptr[d], end = g_rowptr[d + 1];
        float aldd = g_ald[d];
        float acc0 = 0.f, acc1 = 0.f, dn = 0.f;
        for (int base = beg; base < end; base += 32) {
            int cnt = min(32, end - base);
            int si = 0; float ex = 0.f;
            if (lane < cnt) {
                si = g_csr[base + lane];
                ex = __expf(lrelu(g_als[si] + aldd));
            }
            dn += ex;
            int j = 0;
            for (; j + 4 <= cnt; j += 4) {
                int s0 = __shfl_sync(0xffffffffu, si, j);
                int s1 = __shfl_sync(0xffffffffu, si, j + 1);
                int s2 = __shfl_sync(0xffffffffu, si, j + 2);
                int s3 = __shfl_sync(0xffffffffu, si, j + 3);
                float w0 = __shfl_sync(0xffffffffu, ex, j);
                float w1 = __shfl_sync(0xffffffffu, ex, j + 1);
                float w2 = __shfl_sync(0xffffffffu, ex, j + 2);
                float w3 = __shfl_sync(0xffffffffu, ex, j + 3);
                float2 v0 = *(const float2*)&g_xh[s0 * 64 + c2];
                float2 v1 = *(const float2*)&g_xh[s1 * 64 + c2];
                float2 v2 = *(const float2*)&g_xh[s2 * 64 + c2];
                float2 v3 = *(const float2*)&g_xh[s3 * 64 + c2];
                acc0 += w0 * v0.x; acc1 += w0 * v0.y;
                acc0 += w1 * v1.x; acc1 += w1 * v1.y;
                acc0 += w2 * v2.x; acc1 += w2 * v2.y;
                acc0 += w3 * v3.x; acc1 += w3 * v3.y;
            }
            for (; j < cnt; j++) {
                int s0 = __shfl_sync(0xffffffffu, si, j);
                float w0 = __shfl_sync(0xffffffffu, ex, j);
                float2 v0 = *(const float2*)&g_xh[s0 * 64 + c2];
                acc0 += w0 * v0.x; acc1 += w0 * v0.y;
            }
        }
        {
            float ex = __expf(lrelu(g_als[d] + aldd));
            if (lane == 0) dn += ex;
            float2 v = *(const float2*)&g_xh[d * 64 + c2];
            acc0 += ex * v.x; acc1 += ex * v.y;
        }
#pragma unroll
        for (int o = 16; o > 0; o >>= 1) dn += __shfl_xor_sync(0xffffffffu, dn, o);
        float rd = 1.f / (dn + 1e-16f);
        float o0 = acc0 * rd, o1 = acc1 * rd;
        *(float2*)&g_agg2[d * 64 + c2] = make_float2(o0, o1);
        atomicAdd(&ssum[c2], o0);     atomicAdd(&ssum[c2 + 1], o1);
        atomicAdd(&ssq[c2], o0 * o0); atomicAdd(&ssq[c2 + 1], o1 * o1);
    }
    __syncthreads();
    if (tid < 64) {
        atomicAdd(&g_bnsum[tid], ssum[tid]);
        atomicAdd(&g_bnsq[tid], ssq[tid]);
    }
}

// ---------------- BN finalize (+ re-zero stats for next use) ----------------
__global__ void k_bnfin(const float* __restrict__ gamma, const float* __restrict__ beta, int nN) {
    int c = threadIdx.x;
    if (c >= 64) return;
    float inv = 1.f / (float)nN;
    float mu = g_bnsum[c] * inv;
    float var = g_bnsq[c] * inv - mu * mu;
    float rs = rsqrtf(fmaxf(var, 0.f) + 1e-5f);
    float sc = gamma[c] * rs;
    g_scale[c] = sc;
    g_shift[c] = beta[c] - mu * sc;
    g_bnsum[c] = 0.f;
    g_bnsq[c] = 0.f;
    // GAT bias b cancels exactly inside BN, never applied
}

// ---------------- pooling ----------------
__global__ void k_pool(const int* __restrict__ batch, int nN) {
    int t = blockIdx.x * blockDim.x + threadIdx.x;
    if (t >= nN * 64) return;
    int n = t >> 6, c = t & 63;
    int g = batch[n];
    float y = eluf(g_scale[c] * g_agg2[t] + g_shift[c]);
    atomicAdd(&g_psum[g * 64 + c], y);
    atomicMax(&g_pmax[g * 64 + c], fenc(y));
    if (c == 0) atomicAdd(&g_cnt[g], 1.f);
}

// ---------------- final projection ----------------
__global__ __launch_bounds__(128) void k_final(const float* __restrict__ Wout,
                                               const float* __restrict__ bout,
                                               float* __restrict__ out) {
    __shared__ float comb[128];
    int g = blockIdx.x, c = threadIdx.x;
    float cnt = g_cnt[g];
    if (c < 64) {
        comb[c] = (cnt > 0.f) ? fdec(g_pmax[g * 64 + c]) : 0.f;
    } else {
        comb[c] = g_psum[g * 64 + (c - 64)] / fmaxf(cnt, 1.f);
    }
    __syncthreads();
    float acc = bout[c];
#pragma unroll 16
    for (int k = 0; k < 128; k++) acc += comb[k] * Wout[k * 128 + c];
    out[g * 128 + c] = acc;
}

// ---------------- launcher ----------------
extern "C" void kernel_launch(void* const* d_in, const int* in_sizes, int n_in,
                              void* d_out, int out_size) {
    const float* x     = (const float*)d_in[0];
    const int*   ei    = (const int*)d_in[1];
    const int*   batch = (const int*)d_in[2];
    const float* Wemb  = (const float*)d_in[3];
    const float* bemb  = (const float*)d_in[4];
    const float* W1    = (const float*)d_in[5];
    const float* a1s   = (const float*)d_in[6];
    const float* a1d   = (const float*)d_in[7];
    // d_in[8] = b1 (cancels in BN)
    const float* g1    = (const float*)d_in[9];
    const float* be1   = (const float*)d_in[10];
    const float* W2    = (const float*)d_in[11];
    const float* a2s   = (const float*)d_in[12];
    const float* a2d   = (const float*)d_in[13];
    // d_in[14] = b2 (cancels in BN)
    const float* g2    = (const float*)d_in[15];
    const float* be2   = (const float*)d_in[16];
    const float* Wout  = (const float*)d_in[17];
    const float* bout  = (const float*)d_in[18];
    float* out = (float*)d_out;

    int nN = in_sizes[2];
    int E  = in_sizes[1] / 2;
    const int* src = ei;
    const int* dst = ei + E;

    k_init<<<1024, 256>>>();

    // ---- CSR by dst (built once, shared by both convs) ----
    k_hist<<<(E + 255) / 256, 256>>>(dst, E);
    int nb = (nN + SCAN_B - 1) / SCAN_B;
    k_scan_a<<<nb, SCAN_B>>>(nN);
    k_scan_b<<<1, 128>>>(nb);
    k_scan_c<<<(nN + 255) / 256, 256>>>(nN);
    k_fill<<<(E + 255) / 256, 256>>>(src, dst, E);

    // ---- conv1 (heads=2, out=32) ----
    k_node1<<<(nN + 31) / 32, 256>>>(x, Wemb, bemb, W1, a1s, a1d, nN);
    k_gat1<<<(nN * 32 + 255) / 256, 256>>>(nN);
    k_bnfin<<<1, 64>>>(g1, be1, nN);

    // ---- conv2 (heads=1, out=64) ----
    k_node2<<<(nN + 31) / 32, 256>>>(W2, a2s, a2d, nN);
    k_gat2<<<(nN * 32 + 255) / 256, 256>>>(nN);
    k_bnfin<<<1, 64>>>(g2, be2, nN);

    // ---- pool + projection ----
    k_pool<<<(nN * 64 + 255) / 256, 256>>>(batch, nN);
    k_final<<<NG, 128>>>(Wout, bout, out);
}

// round 15
// speedup vs baseline: 2.0288x; 1.3080x over previous
#include <cuda_runtime.h>
#include <cuda_fp16.h>

#define NN 100000
#define NE 3200000
#define NG 256
#define SCAN_B 1024
#define PNODES 64

// ---------------- scratch (device globals; no allocation allowed) ----------------
__device__ int      g_deg[NN];
__device__ int      g_rowptr[NN + 1];
__device__ int      g_cursor[NN];
__device__ int      g_csr[NE];          // src ids grouped by dst
__device__ int      g_bsum[256];
__device__ __half2  g_xhh[NN * 32];     // transformed features, fp16x2 (ch 2l,2l+1)
__device__ float    g_agg1[NN * 64];    // conv1 output (normalized, pre-BN)
__device__ float    g_agg2[NN * 64];    // conv2 output (normalized, pre-BN)
__device__ float    g_als[NN * 2];      // attention src logits (fp32)
__device__ float    g_ald[NN * 2];      // attention dst logits (fp32)
__device__ float    g_bnsum[64];
__device__ float    g_bnsq[64];
__device__ float    g_scale[64];
__device__ float    g_shift[64];
__device__ float    g_psum[NG * 64];
__device__ unsigned g_pmax[NG * 64];
__device__ float    g_cnt[NG];

// ---------------- helpers ----------------
__device__ __forceinline__ float eluf(float x)  { return x > 0.f ? x : (__expf(x) - 1.f); }
__device__ __forceinline__ float lrelu(float x) { return x > 0.f ? x : 0.2f * x; }

__device__ __forceinline__ unsigned fenc(float f) {
    unsigned u = __float_as_uint(f);
    return (u & 0x80000000u) ? ~u : (u | 0x80000000u);
}
__device__ __forceinline__ float fdec(unsigned e) {
    return (e & 0x80000000u) ? __uint_as_float(e ^ 0x80000000u) : __uint_as_float(~e);
}
__device__ __forceinline__ float2 ldxh(int node, int l) {
    return __half22float2(g_xhh[node * 32 + l]);
}

// ---------------- zero / init ----------------
__global__ void k_init() {
    int i = blockIdx.x * blockDim.x + threadIdx.x;
    int stride = gridDim.x * blockDim.x;
    for (int j = i; j < NN; j += stride) g_deg[j] = 0;
    for (int j = i; j < NG * 64; j += stride) { g_psum[j] = 0.f; g_pmax[j] = 0u; }
    if (i < NG) g_cnt[i] = 0.f;
    if (i < 64) { g_bnsum[i] = 0.f; g_bnsq[i] = 0.f; }
}

// ---------------- CSR build ----------------
__global__ void k_hist(const int* __restrict__ dst, int E) {
    int e = blockIdx.x * blockDim.x + threadIdx.x;
    if (e < E) atomicAdd(&g_deg[dst[e]], 1);
}

__global__ __launch_bounds__(SCAN_B) void k_scan_a(int n) {
    __shared__ int sh[SCAN_B];
    int tid = threadIdx.x;
    int i = blockIdx.x * SCAN_B + tid;
    int v = (i < n) ? g_deg[i] : 0;
    sh[tid] = v;
    __syncthreads();
    for (int o = 1; o < SCAN_B; o <<= 1) {
        int t = (tid >= o) ? sh[tid - o] : 0;
        __syncthreads();
        sh[tid] += t;
        __syncthreads();
    }
    if (i < n) g_cursor[i] = sh[tid];
    if (tid == SCAN_B - 1) g_bsum[blockIdx.x] = sh[tid];
}

__global__ __launch_bounds__(128) void k_scan_b(int nb) {
    __shared__ int sh[128];
    int tid = threadIdx.x;
    int v = (tid < nb) ? g_bsum[tid] : 0;
    sh[tid] = v;
    __syncthreads();
    for (int o = 1; o < 128; o <<= 1) {
        int t = (tid >= o) ? sh[tid - o] : 0;
        __syncthreads();
        sh[tid] += t;
        __syncthreads();
    }
    if (tid < nb) g_bsum[tid] = sh[tid] - v;
}

__global__ void k_scan_c(int n) {
    int i = blockIdx.x * blockDim.x + threadIdx.x;
    if (i >= n) return;
    int off = g_bsum[i / SCAN_B];
    int incl = g_cursor[i];
    int rp = off + incl - g_deg[i];
    g_rowptr[i] = rp;
    g_cursor[i] = rp;
    if (i == n - 1) g_rowptr[n] = off + incl;
}

__global__ void k_fill(const int* __restrict__ src, const int* __restrict__ dst, int E) {
    int e = blockIdx.x * blockDim.x + threadIdx.x;
    if (e >= E) return;
    int d = dst[e];
    int pos = atomicAdd(&g_cursor[d], 1);
    g_csr[pos] = src[e];
}

// ---------------- node kernels: transform + 64x64 GEMM + logits + fp16 store ----------------
__global__ __launch_bounds__(256) void k_node1(const float* __restrict__ x,
                                               const float* __restrict__ Wemb,
                                               const float* __restrict__ bemb,
                                               const float* __restrict__ W1,
                                               const float* __restrict__ a1s,
                                               const float* __restrict__ a1d, int nN) {
    __shared__ __align__(16) float sW[4096];
    __shared__ float sWe[256];
    __shared__ float sbe[64];
    __shared__ float sx[128];
    __shared__ float sh[2048];
    int tid = threadIdx.x;
    int n0 = blockIdx.x * 32;
    for (int i = tid; i < 4096; i += 256) sW[i] = W1[i];
    if (tid < 256) sWe[tid] = Wemb[tid];
    if (tid < 64) sbe[tid] = bemb[tid];
    if (tid < 128) {
        int n = tid >> 2, k = tid & 3;
        int node = n0 + n;
        sx[tid] = node < nN ? x[node * 4 + k] : 0.f;
    }
    __syncthreads();
    for (int i = tid; i < 2048; i += 256) {
        int n = i >> 6, c = i & 63;
        float acc = sbe[c];
#pragma unroll
        for (int k = 0; k < 4; k++) acc += sx[n * 4 + k] * sWe[k * 64 + c];
        sh[i] = eluf(acc);
    }
    __syncthreads();
    int w = tid >> 5, l = tid & 31;
    int c = l * 2;
    float2 avs = *(const float2*)&a1s[c];
    float2 avd = *(const float2*)&a1d[c];
    float acc[4][2] = {};
#pragma unroll 8
    for (int k = 0; k < 64; k++) {
        float2 wv = *(const float2*)&sW[k * 64 + c];
#pragma unroll
        for (int j = 0; j < 4; j++) {
            float hv = sh[(w + j * 8) * 64 + k];
            acc[j][0] += hv * wv.x;
            acc[j][1] += hv * wv.y;
        }
    }
#pragma unroll
    for (int j = 0; j < 4; j++) {
        int node = n0 + w + j * 8;
        if (node < nN)
            g_xhh[node * 32 + l] = __float22half2_rn(make_float2(acc[j][0], acc[j][1]));
        float ps = avs.x * acc[j][0] + avs.y * acc[j][1];
        float pd = avd.x * acc[j][0] + avd.y * acc[j][1];
#pragma unroll
        for (int o = 1; o < 16; o <<= 1) {
            ps += __shfl_xor_sync(0xffffffffu, ps, o);
            pd += __shfl_xor_sync(0xffffffffu, pd, o);
        }
        if (node < nN) {
            if (l == 0)  { g_als[node * 2]     = ps; g_ald[node * 2]     = pd; }
            if (l == 16) { g_als[node * 2 + 1] = ps; g_ald[node * 2 + 1] = pd; }
        }
    }
}

__global__ __launch_bounds__(256) void k_node2(const float* __restrict__ W2,
                                               const float* __restrict__ a2s,
                                               const float* __restrict__ a2d, int nN) {
    __shared__ __align__(16) float sW[4096];
    __shared__ float ssc[64];
    __shared__ float ssh[64];
    __shared__ float sh[2048];
    int tid = threadIdx.x;
    int n0 = blockIdx.x * 32;
    for (int i = tid; i < 4096; i += 256) sW[i] = W2[i];
    if (tid < 64) { ssc[tid] = g_scale[tid]; ssh[tid] = g_shift[tid]; }
    __syncthreads();
    for (int i = tid; i < 2048; i += 256) {
        int n = i >> 6, c = i & 63;
        int node = n0 + n;
        float v = node < nN ? g_agg1[node * 64 + c] : 0.f;
        sh[i] = eluf(ssc[c] * v + ssh[c]);
    }
    __syncthreads();
    int w = tid >> 5, l = tid & 31;
    int c = l * 2;
    float2 avs = *(const float2*)&a2s[c];
    float2 avd = *(const float2*)&a2d[c];
    float acc[4][2] = {};
#pragma unroll 8
    for (int k = 0; k < 64; k++) {
        float2 wv = *(const float2*)&sW[k * 64 + c];
#pragma unroll
        for (int j = 0; j < 4; j++) {
            float hv = sh[(w + j * 8) * 64 + k];
            acc[j][0] += hv * wv.x;
            acc[j][1] += hv * wv.y;
        }
    }
#pragma unroll
    for (int j = 0; j < 4; j++) {
        int node = n0 + w + j * 8;
        if (node < nN)
            g_xhh[node * 32 + l] = __float22half2_rn(make_float2(acc[j][0], acc[j][1]));
        float ps = avs.x * acc[j][0] + avs.y * acc[j][1];
        float pd = avd.x * acc[j][0] + avd.y * acc[j][1];
#pragma unroll
        for (int o = 1; o < 32; o <<= 1) {
            ps += __shfl_xor_sync(0xffffffffu, ps, o);
            pd += __shfl_xor_sync(0xffffffffu, pd, o);
        }
        if (node < nN && l == 0) { g_als[node] = ps; g_ald[node] = pd; }
    }
}

// ---------------- GAT aggregation: warp per dst, fp16 gather, fused BN stats ----------------
__global__ __launch_bounds__(256) void k_gat1(int nN) {
    __shared__ float ssum[64];
    __shared__ float ssq[64];
    int tid = threadIdx.x;
    if (tid < 64) { ssum[tid] = 0.f; ssq[tid] = 0.f; }
    __syncthreads();
    int d = (blockIdx.x * 256 + tid) >> 5;
    int lane = tid & 31;
    int c2 = lane * 2;
    if (d < nN) {
        int beg = g_rowptr[d], end = g_rowptr[d + 1];
        float2 aldd = *(const float2*)&g_ald[d * 2];
        float acc0 = 0.f, acc1 = 0.f, dn0 = 0.f, dn1 = 0.f;
        for (int base = beg; base < end; base += 32) {
            int cnt = min(32, end - base);
            int si = 0; float ex0 = 0.f, ex1 = 0.f;
            if (lane < cnt) {
                si = g_csr[base + lane];
                float2 as = *(const float2*)&g_als[si * 2];
                ex0 = __expf(lrelu(as.x + aldd.x));
                ex1 = __expf(lrelu(as.y + aldd.y));
            }
            dn0 += ex0; dn1 += ex1;
            int j = 0;
            for (; j + 4 <= cnt; j += 4) {
                int s0 = __shfl_sync(0xffffffffu, si, j);
                int s1 = __shfl_sync(0xffffffffu, si, j + 1);
                int s2 = __shfl_sync(0xffffffffu, si, j + 2);
                int s3 = __shfl_sync(0xffffffffu, si, j + 3);
                float a0 = __shfl_sync(0xffffffffu, ex0, j),     b0 = __shfl_sync(0xffffffffu, ex1, j);
                float a1 = __shfl_sync(0xffffffffu, ex0, j + 1), b1 = __shfl_sync(0xffffffffu, ex1, j + 1);
                float a2 = __shfl_sync(0xffffffffu, ex0, j + 2), b2 = __shfl_sync(0xffffffffu, ex1, j + 2);
                float a3 = __shfl_sync(0xffffffffu, ex0, j + 3), b3 = __shfl_sync(0xffffffffu, ex1, j + 3);
                float2 v0 = ldxh(s0, lane);
                float2 v1 = ldxh(s1, lane);
                float2 v2 = ldxh(s2, lane);
                float2 v3 = ldxh(s3, lane);
                float w0 = lane < 16 ? a0 : b0;
                float w1 = lane < 16 ? a1 : b1;
                float w2 = lane < 16 ? a2 : b2;
                float w3 = lane < 16 ? a3 : b3;
                acc0 += w0 * v0.x; acc1 += w0 * v0.y;
                acc0 += w1 * v1.x; acc1 += w1 * v1.y;
                acc0 += w2 * v2.x; acc1 += w2 * v2.y;
                acc0 += w3 * v3.x; acc1 += w3 * v3.y;
            }
            for (; j < cnt; j++) {
                int s0 = __shfl_sync(0xffffffffu, si, j);
                float a0 = __shfl_sync(0xffffffffu, ex0, j), b0 = __shfl_sync(0xffffffffu, ex1, j);
                float w0 = lane < 16 ? a0 : b0;
                float2 v0 = ldxh(s0, lane);
                acc0 += w0 * v0.x; acc1 += w0 * v0.y;
            }
        }
        // self loop
        {
            float2 as = *(const float2*)&g_als[d * 2];
            float ex0 = __expf(lrelu(as.x + aldd.x));
            float ex1 = __expf(lrelu(as.y + aldd.y));
            if (lane == 0) { dn0 += ex0; dn1 += ex1; }
            float w = lane < 16 ? ex0 : ex1;
            float2 v = ldxh(d, lane);
            acc0 += w * v.x; acc1 += w * v.y;
        }
#pragma unroll
        for (int o = 16; o > 0; o >>= 1) {
            dn0 += __shfl_xor_sync(0xffffffffu, dn0, o);
            dn1 += __shfl_xor_sync(0xffffffffu, dn1, o);
        }
        float rd = 1.f / (((lane < 16) ? dn0 : dn1) + 1e-16f);
        float o0 = acc0 * rd, o1 = acc1 * rd;
        *(float2*)&g_agg1[d * 64 + c2] = make_float2(o0, o1);
        atomicAdd(&ssum[c2], o0);     atomicAdd(&ssum[c2 + 1], o1);
        atomicAdd(&ssq[c2], o0 * o0); atomicAdd(&ssq[c2 + 1], o1 * o1);
    }
    __syncthreads();
    if (tid < 64) {
        atomicAdd(&g_bnsum[tid], ssum[tid]);
        atomicAdd(&g_bnsq[tid], ssq[tid]);
    }
}

__global__ __launch_bounds__(256) void k_gat2(int nN) {
    __shared__ float ssum[64];
    __shared__ float ssq[64];
    int tid = threadIdx.x;
    if (tid < 64) { ssum[tid] = 0.f; ssq[tid] = 0.f; }
    __syncthreads();
    int d = (blockIdx.x * 256 + tid) >> 5;
    int lane = tid & 31;
    int c2 = lane * 2;
    if (d < nN) {
        int beg = g_rowptr[d], end = g_rowptr[d + 1];
        float aldd = g_ald[d];
        float acc0 = 0.f, acc1 = 0.f, dn = 0.f;
        for (int base = beg; base < end; base += 32) {
            int cnt = min(32, end - base);
            int si = 0; float ex = 0.f;
            if (lane < cnt) {
                si = g_csr[base + lane];
                ex = __expf(lrelu(g_als[si] + aldd));
            }
            dn += ex;
            int j = 0;
            for (; j + 4 <= cnt; j += 4) {
                int s0 = __shfl_sync(0xffffffffu, si, j);
                int s1 = __shfl_sync(0xffffffffu, si, j + 1);
                int s2 = __shfl_sync(0xffffffffu, si, j + 2);
                int s3 = __shfl_sync(0xffffffffu, si, j + 3);
                float w0 = __shfl_sync(0xffffffffu, ex, j);
                float w1 = __shfl_sync(0xffffffffu, ex, j + 1);
                float w2 = __shfl_sync(0xffffffffu, ex, j + 2);
                float w3 = __shfl_sync(0xffffffffu, ex, j + 3);
                float2 v0 = ldxh(s0, lane);
                float2 v1 = ldxh(s1, lane);
                float2 v2 = ldxh(s2, lane);
                float2 v3 = ldxh(s3, lane);
                acc0 += w0 * v0.x; acc1 += w0 * v0.y;
                acc0 += w1 * v1.x; acc1 += w1 * v1.y;
                acc0 += w2 * v2.x; acc1 += w2 * v2.y;
                acc0 += w3 * v3.x; acc1 += w3 * v3.y;
            }
            for (; j < cnt; j++) {
                int s0 = __shfl_sync(0xffffffffu, si, j);
                float w0 = __shfl_sync(0xffffffffu, ex, j);
                float2 v0 = ldxh(s0, lane);
                acc0 += w0 * v0.x; acc1 += w0 * v0.y;
            }
        }
        {
            float ex = __expf(lrelu(g_als[d] + aldd));
            if (lane == 0) dn += ex;
            float2 v = ldxh(d, lane);
            acc0 += ex * v.x; acc1 += ex * v.y;
        }
#pragma unroll
        for (int o = 16; o > 0; o >>= 1) dn += __shfl_xor_sync(0xffffffffu, dn, o);
        float rd = 1.f / (dn + 1e-16f);
        float o0 = acc0 * rd, o1 = acc1 * rd;
        *(float2*)&g_agg2[d * 64 + c2] = make_float2(o0, o1);
        atomicAdd(&ssum[c2], o0);     atomicAdd(&ssum[c2 + 1], o1);
        atomicAdd(&ssq[c2], o0 * o0); atomicAdd(&ssq[c2 + 1], o1 * o1);
    }
    __syncthreads();
    if (tid < 64) {
        atomicAdd(&g_bnsum[tid], ssum[tid]);
        atomicAdd(&g_bnsq[tid], ssq[tid]);
    }
}

// ---------------- BN finalize (+ re-zero stats) ----------------
__global__ void k_bnfin(const float* __restrict__ gamma, const float* __restrict__ beta, int nN) {
    int c = threadIdx.x;
    if (c >= 64) return;
    float inv = 1.f / (float)nN;
    float mu = g_bnsum[c] * inv;
    float var = g_bnsq[c] * inv - mu * mu;
    float rs = rsqrtf(fmaxf(var, 0.f) + 1e-5f);
    float sc = gamma[c] * rs;
    g_scale[c] = sc;
    g_shift[c] = beta[c] - mu * sc;
    g_bnsum[c] = 0.f;
    g_bnsq[c] = 0.f;
}

// ---------------- pooling: privatized per 64-node chunk (batch is sorted) ----------------
__global__ __launch_bounds__(256) void k_pool(const int* __restrict__ batch, int nN) {
    __shared__ float ssum[256];
    __shared__ float smax[256];
    int tid = threadIdx.x;
    int n0 = blockIdx.x * PNODES;
    if (n0 >= nN) return;
    int nEnd = min(n0 + PNODES, nN);
    int c = tid & 63, r = tid >> 6;
    int g0 = batch[n0];
    int g1 = batch[nEnd - 1];
    if (g0 == g1) {
        float sc = g_scale[c], sh = g_shift[c];
        float s = 0.f, m = -3.4e38f;
        for (int n = n0 + r; n < nEnd; n += 4) {
            float y = eluf(sc * g_agg2[n * 64 + c] + sh);
            s += y; m = fmaxf(m, y);
        }
        ssum[tid] = s; smax[tid] = m;
        __syncthreads();
        if (r == 0) {
            s = ssum[c] + ssum[64 + c] + ssum[128 + c] + ssum[192 + c];
            m = fmaxf(fmaxf(smax[c], smax[64 + c]), fmaxf(smax[128 + c], smax[192 + c]));
            atomicAdd(&g_psum[g0 * 64 + c], s);
            atomicMax(&g_pmax[g0 * 64 + c], fenc(m));
            if (c == 0) atomicAdd(&g_cnt[g0], (float)(nEnd - n0));
        }
    } else {
        int tot = (nEnd - n0) * 64;
        for (int i = tid; i < tot; i += 256) {
            int n = n0 + (i >> 6);
            int cc = i & 63;
            int g = batch[n];
            float y = eluf(g_scale[cc] * g_agg2[n * 64 + cc] + g_shift[cc]);
            atomicAdd(&g_psum[g * 64 + cc], y);
            atomicMax(&g_pmax[g * 64 + cc], fenc(y));
            if (cc == 0) atomicAdd(&g_cnt[g], 1.f);
        }
    }
}

// ---------------- final projection ----------------
__global__ __launch_bounds__(128) void k_final(const float* __restrict__ Wout,
                                               const float* __restrict__ bout,
                                               float* __restrict__ out) {
    __shared__ float comb[128];
    int g = blockIdx.x, c = threadIdx.x;
    float cnt = g_cnt[g];
    if (c < 64) {
        comb[c] = (cnt > 0.f) ? fdec(g_pmax[g * 64 + c]) : 0.f;
    } else {
        comb[c] = g_psum[g * 64 + (c - 64)] / fmaxf(cnt, 1.f);
    }
    __syncthreads();
    float acc = bout[c];
#pragma unroll 16
    for (int k = 0; k < 128; k++) acc += comb[k] * Wout[k * 128 + c];
    out[g * 128 + c] = acc;
}

// ---------------- launcher ----------------
extern "C" void kernel_launch(void* const* d_in, const int* in_sizes, int n_in,
                              void* d_out, int out_size) {
    const float* x     = (const float*)d_in[0];
    const int*   ei    = (const int*)d_in[1];
    const int*   batch = (const int*)d_in[2];
    const float* Wemb  = (const float*)d_in[3];
    const float* bemb  = (const float*)d_in[4];
    const float* W1    = (const float*)d_in[5];
    const float* a1s   = (const float*)d_in[6];
    const float* a1d   = (const float*)d_in[7];
    // d_in[8] = b1 (cancels in BN)
    const float* g1    = (const float*)d_in[9];
    const float* be1   = (const float*)d_in[10];
    const float* W2    = (const float*)d_in[11];
    const float* a2s   = (const float*)d_in[12];
    const float* a2d   = (const float*)d_in[13];
    // d_in[14] = b2 (cancels in BN)
    const float* g2    = (const float*)d_in[15];
    const float* be2   = (const float*)d_in[16];
    const float* Wout  = (const float*)d_in[17];
    const float* bout  = (const float*)d_in[18];
    float* out = (float*)d_out;

    int nN = in_sizes[2];
    int E  = in_sizes[1] / 2;
    const int* src = ei;
    const int* dst = ei + E;

    k_init<<<1024, 256>>>();

    // ---- CSR by dst (built once, shared by both convs) ----
    k_hist<<<(E + 255) / 256, 256>>>(dst, E);
    int nb = (nN + SCAN_B - 1) / SCAN_B;
    k_scan_a<<<nb, SCAN_B>>>(nN);
    k_scan_b<<<1, 128>>>(nb);
    k_scan_c<<<(nN + 255) / 256, 256>>>(nN);
    k_fill<<<(E + 255) / 256, 256>>>(src, dst, E);

    // ---- conv1 (heads=2, out=32) ----
    k_node1<<<(nN + 31) / 32, 256>>>(x, Wemb, bemb, W1, a1s, a1d, nN);
    k_gat1<<<(nN * 32 + 255) / 256, 256>>>(nN);
    k_bnfin<<<1, 64>>>(g1, be1, nN);

    // ---- conv2 (heads=1, out=64) ----
    k_node2<<<(nN + 31) / 32, 256>>>(W2, a2s, a2d, nN);
    k_gat2<<<(nN * 32 + 255) / 256, 256>>>(nN);
    k_bnfin<<<1, 64>>>(g2, be2, nN);

    // ---- pool + projection ----
    k_pool<<<(nN + PNODES - 1) / PNODES, 256>>>(batch, nN);
    k_final<<<NG, 128>>>(Wout, bout, out);
}

// round 17
// speedup vs baseline: 2.0355x; 1.0033x over previous
#include <cuda_runtime.h>
#include <cuda_fp16.h>

#define NN 100000
#define NE 3200000
#define NG 256
#define SCAN_B 1024
#define PNODES 64

// ---------------- scratch (device globals; no allocation allowed) ----------------
__device__ int      g_deg[NN];
__device__ int      g_rowptr[NN + 1];
__device__ int      g_cursor[NN];
__device__ int      g_csr[NE];          // src ids grouped by dst
__device__ int      g_bsum[256];
__device__ __half2  g_xhh[NN * 32];     // transformed features, fp16x2 (ch 2l,2l+1)
__device__ float    g_agg1[NN * 64];    // conv1 output (normalized, pre-BN)
__device__ float    g_agg2[NN * 64];    // conv2 output (normalized, pre-BN)
__device__ float    g_als[NN * 2];      // attention src logits (fp32)
__device__ float    g_ald[NN * 2];      // attention dst logits (fp32)
__device__ float    g_bnsum[64];
__device__ float    g_bnsq[64];
__device__ float    g_scale[64];
__device__ float    g_shift[64];
__device__ float    g_psum[NG * 64];
__device__ unsigned g_pmax[NG * 64];
__device__ float    g_cnt[NG];

// ---------------- helpers ----------------
__device__ __forceinline__ float eluf(float x)  { return x > 0.f ? x : (__expf(x) - 1.f); }
__device__ __forceinline__ float lrelu(float x) { return x > 0.f ? x : 0.2f * x; }

__device__ __forceinline__ unsigned fenc(float f) {
    unsigned u = __float_as_uint(f);
    return (u & 0x80000000u) ? ~u : (u | 0x80000000u);
}
__device__ __forceinline__ float fdec(unsigned e) {
    return (e & 0x80000000u) ? __uint_as_float(e ^ 0x80000000u) : __uint_as_float(~e);
}
__device__ __forceinline__ float2 ldxh(int node, int l) {
    return __half22float2(g_xhh[node * 32 + l]);
}

// ---------------- zero / init ----------------
__global__ void k_init() {
    int i = blockIdx.x * blockDim.x + threadIdx.x;
    int stride = gridDim.x * blockDim.x;
    for (int j = i; j < NN; j += stride) g_deg[j] = 0;
    for (int j = i; j < NG * 64; j += stride) { g_psum[j] = 0.f; g_pmax[j] = 0u; }
    if (i < NG) g_cnt[i] = 0.f;
    if (i < 64) { g_bnsum[i] = 0.f; g_bnsq[i] = 0.f; }
}

// ---------------- CSR build ----------------
__global__ void k_hist(const int* __restrict__ dst, int E) {
    int e = blockIdx.x * blockDim.x + threadIdx.x;
    if (e < E) atomicAdd(&g_deg[dst[e]], 1);
}

__global__ __launch_bounds__(SCAN_B) void k_scan_a(int n) {
    __shared__ int sh[SCAN_B];
    int tid = threadIdx.x;
    int i = blockIdx.x * SCAN_B + tid;
    int v = (i < n) ? g_deg[i] : 0;
    sh[tid] = v;
    __syncthreads();
    for (int o = 1; o < SCAN_B; o <<= 1) {
        int t = (tid >= o) ? sh[tid - o] : 0;
        __syncthreads();
        sh[tid] += t;
        __syncthreads();
    }
    if (i < n) g_cursor[i] = sh[tid];
    if (tid == SCAN_B - 1) g_bsum[blockIdx.x] = sh[tid];
}

__global__ __launch_bounds__(128) void k_scan_b(int nb) {
    __shared__ int sh[128];
    int tid = threadIdx.x;
    int v = (tid < nb) ? g_bsum[tid] : 0;
    sh[tid] = v;
    __syncthreads();
    for (int o = 1; o < 128; o <<= 1) {
        int t = (tid >= o) ? sh[tid - o] : 0;
        __syncthreads();
        sh[tid] += t;
        __syncthreads();
    }
    if (tid < nb) g_bsum[tid] = sh[tid] - v;
}

__global__ void k_scan_c(int n) {
    int i = blockIdx.x * blockDim.x + threadIdx.x;
    if (i >= n) return;
    int off = g_bsum[i / SCAN_B];
    int incl = g_cursor[i];
    int rp = off + incl - g_deg[i];
    g_rowptr[i] = rp;
    g_cursor[i] = rp;
    if (i == n - 1) g_rowptr[n] = off + incl;
}

__global__ void k_fill(const int* __restrict__ src, const int* __restrict__ dst, int E) {
    int e = blockIdx.x * blockDim.x + threadIdx.x;
    if (e >= E) return;
    int d = dst[e];
    int pos = atomicAdd(&g_cursor[d], 1);
    g_csr[pos] = src[e];
}

// ---------------- node kernels: transform + 64x64 GEMM + logits + fp16 store ----------------
__global__ __launch_bounds__(256) void k_node1(const float* __restrict__ x,
                                               const float* __restrict__ Wemb,
                                               const float* __restrict__ bemb,
                                               const float* __restrict__ W1,
                                               const float* __restrict__ a1s,
                                               const float* __restrict__ a1d, int nN) {
    __shared__ __align__(16) float sW[4096];
    __shared__ float sWe[256];
    __shared__ float sbe[64];
    __shared__ float sx[128];
    __shared__ float sh[2048];
    int tid = threadIdx.x;
    int n0 = blockIdx.x * 32;
    for (int i = tid; i < 4096; i += 256) sW[i] = W1[i];
    if (tid < 256) sWe[tid] = Wemb[tid];
    if (tid < 64) sbe[tid] = bemb[tid];
    if (tid < 128) {
        int n = tid >> 2, k = tid & 3;
        int node = n0 + n;
        sx[tid] = node < nN ? x[node * 4 + k] : 0.f;
    }
    __syncthreads();
    for (int i = tid; i < 2048; i += 256) {
        int n = i >> 6, c = i & 63;
        float acc = sbe[c];
#pragma unroll
        for (int k = 0; k < 4; k++) acc += sx[n * 4 + k] * sWe[k * 64 + c];
        sh[i] = eluf(acc);
    }
    __syncthreads();
    int w = tid >> 5, l = tid & 31;
    int c = l * 2;
    float2 avs = *(const float2*)&a1s[c];
    float2 avd = *(const float2*)&a1d[c];
    float acc[4][2] = {};
#pragma unroll 8
    for (int k = 0; k < 64; k++) {
        float2 wv = *(const float2*)&sW[k * 64 + c];
#pragma unroll
        for (int j = 0; j < 4; j++) {
            float hv = sh[(w + j * 8) * 64 + k];
            acc[j][0] += hv * wv.x;
            acc[j][1] += hv * wv.y;
        }
    }
#pragma unroll
    for (int j = 0; j < 4; j++) {
        int node = n0 + w + j * 8;
        if (node < nN)
            g_xhh[node * 32 + l] = __float22half2_rn(make_float2(acc[j][0], acc[j][1]));
        float ps = avs.x * acc[j][0] + avs.y * acc[j][1];
        float pd = avd.x * acc[j][0] + avd.y * acc[j][1];
#pragma unroll
        for (int o = 1; o < 16; o <<= 1) {
            ps += __shfl_xor_sync(0xffffffffu, ps, o);
            pd += __shfl_xor_sync(0xffffffffu, pd, o);
        }
        if (node < nN) {
            if (l == 0)  { g_als[node * 2]     = ps; g_ald[node * 2]     = pd; }
            if (l == 16) { g_als[node * 2 + 1] = ps; g_ald[node * 2 + 1] = pd; }
        }
    }
}

__global__ __launch_bounds__(256) void k_node2(const float* __restrict__ W2,
                                               const float* __restrict__ a2s,
                                               const float* __restrict__ a2d, int nN) {
    __shared__ __align__(16) float sW[4096];
    __shared__ float ssc[64];
    __shared__ float ssh[64];
    __shared__ float sh[2048];
    int tid = threadIdx.x;
    int n0 = blockIdx.x * 32;
    for (int i = tid; i < 4096; i += 256) sW[i] = W2[i];
    if (tid < 64) { ssc[tid] = g_scale[tid]; ssh[tid] = g_shift[tid]; }
    __syncthreads();
    for (int i = tid; i < 2048; i += 256) {
        int n = i >> 6, c = i & 63;
        int node = n0 + n;
        float v = node < nN ? g_agg1[node * 64 + c] : 0.f;
        sh[i] = eluf(ssc[c] * v + ssh[c]);
    }
    __syncthreads();
    int w = tid >> 5, l = tid & 31;
    int c = l * 2;
    float2 avs = *(const float2*)&a2s[c];
    float2 avd = *(const float2*)&a2d[c];
    float acc[4][2] = {};
#pragma unroll 8
    for (int k = 0; k < 64; k++) {
        float2 wv = *(const float2*)&sW[k * 64 + c];
#pragma unroll
        for (int j = 0; j < 4; j++) {
            float hv = sh[(w + j * 8) * 64 + k];
            acc[j][0] += hv * wv.x;
            acc[j][1] += hv * wv.y;
        }
    }
#pragma unroll
    for (int j = 0; j < 4; j++) {
        int node = n0 + w + j * 8;
        if (node < nN)
            g_xhh[node * 32 + l] = __float22half2_rn(make_float2(acc[j][0], acc[j][1]));
        float ps = avs.x * acc[j][0] + avs.y * acc[j][1];
        float pd = avd.x * acc[j][0] + avd.y * acc[j][1];
#pragma unroll
        for (int o = 1; o < 32; o <<= 1) {
            ps += __shfl_xor_sync(0xffffffffu, ps, o);
            pd += __shfl_xor_sync(0xffffffffu, pd, o);
        }
        if (node < nN && l == 0) { g_als[node] = ps; g_ald[node] = pd; }
    }
}

// ---------------- GAT aggregation: warp per dst, fp16 gather, fused BN stats ----------------
__global__ __launch_bounds__(256) void k_gat1(int nN) {
    __shared__ float ssum[64];
    __shared__ float ssq[64];
    int tid = threadIdx.x;
    if (tid < 64) { ssum[tid] = 0.f; ssq[tid] = 0.f; }
    __syncthreads();
    int d = (blockIdx.x * 256 + tid) >> 5;
    int lane = tid & 31;
    int c2 = lane * 2;
    if (d < nN) {
        int beg = g_rowptr[d], end = g_rowptr[d + 1];
        float2 aldd = *(const float2*)&g_ald[d * 2];
        float acc0 = 0.f, acc1 = 0.f, dn0 = 0.f, dn1 = 0.f;
        for (int base = beg; base < end; base += 32) {
            int cnt = min(32, end - base);
            int si = 0; float ex0 = 0.f, ex1 = 0.f;
            if (lane < cnt) {
                si = g_csr[base + lane];
                float2 as = *(const float2*)&g_als[si * 2];
                ex0 = __expf(lrelu(as.x + aldd.x));
                ex1 = __expf(lrelu(as.y + aldd.y));
            }
            dn0 += ex0; dn1 += ex1;
            int j = 0;
            for (; j + 4 <= cnt; j += 4) {
                int s0 = __shfl_sync(0xffffffffu, si, j);
                int s1 = __shfl_sync(0xffffffffu, si, j + 1);
                int s2 = __shfl_sync(0xffffffffu, si, j + 2);
                int s3 = __shfl_sync(0xffffffffu, si, j + 3);
                float a0 = __shfl_sync(0xffffffffu, ex0, j),     b0 = __shfl_sync(0xffffffffu, ex1, j);
                float a1 = __shfl_sync(0xffffffffu, ex0, j + 1), b1 = __shfl_sync(0xffffffffu, ex1, j + 1);
                float a2 = __shfl_sync(0xffffffffu, ex0, j + 2), b2 = __shfl_sync(0xffffffffu, ex1, j + 2);
                float a3 = __shfl_sync(0xffffffffu, ex0, j + 3), b3 = __shfl_sync(0xffffffffu, ex1, j + 3);
                float2 v0 = ldxh(s0, lane);
                float2 v1 = ldxh(s1, lane);
                float2 v2 = ldxh(s2, lane);
                float2 v3 = ldxh(s3, lane);
                float w0 = lane < 16 ? a0 : b0;
                float w1 = lane < 16 ? a1 : b1;
                float w2 = lane < 16 ? a2 : b2;
                float w3 = lane < 16 ? a3 : b3;
                acc0 += w0 * v0.x; acc1 += w0 * v0.y;
                acc0 += w1 * v1.x; acc1 += w1 * v1.y;
                acc0 += w2 * v2.x; acc1 += w2 * v2.y;
                acc0 += w3 * v3.x; acc1 += w3 * v3.y;
            }
            for (; j < cnt; j++) {
                int s0 = __shfl_sync(0xffffffffu, si, j);
                float a0 = __shfl_sync(0xffffffffu, ex0, j), b0 = __shfl_sync(0xffffffffu, ex1, j);
                float w0 = lane < 16 ? a0 : b0;
                float2 v0 = ldxh(s0, lane);
                acc0 += w0 * v0.x; acc1 += w0 * v0.y;
            }
        }
        // self loop
        {
            float2 as = *(const float2*)&g_als[d * 2];
            float ex0 = __expf(lrelu(as.x + aldd.x));
            float ex1 = __expf(lrelu(as.y + aldd.y));
            if (lane == 0) { dn0 += ex0; dn1 += ex1; }
            float w = lane < 16 ? ex0 : ex1;
            float2 v = ldxh(d, lane);
            acc0 += w * v.x; acc1 += w * v.y;
        }
#pragma unroll
        for (int o = 16; o > 0; o >>= 1) {
            dn0 += __shfl_xor_sync(0xffffffffu, dn0, o);
            dn1 += __shfl_xor_sync(0xffffffffu, dn1, o);
        }
        float rd = 1.f / (((lane < 16) ? dn0 : dn1) + 1e-16f);
        float o0 = acc0 * rd, o1 = acc1 * rd;
        *(float2*)&g_agg1[d * 64 + c2] = make_float2(o0, o1);
        atomicAdd(&ssum[c2], o0);     atomicAdd(&ssum[c2 + 1], o1);
        atomicAdd(&ssq[c2], o0 * o0); atomicAdd(&ssq[c2 + 1], o1 * o1);
    }
    __syncthreads();
    if (tid < 64) {
        atomicAdd(&g_bnsum[tid], ssum[tid]);
        atomicAdd(&g_bnsq[tid], ssq[tid]);
    }
}

__global__ __launch_bounds__(256) void k_gat2(int nN) {
    __shared__ float ssum[64];
    __shared__ float ssq[64];
    int tid = threadIdx.x;
    if (tid < 64) { ssum[tid] = 0.f; ssq[tid] = 0.f; }
    __syncthreads();
    int d = (blockIdx.x * 256 + tid) >> 5;
    int lane = tid & 31;
    int c2 = lane * 2;
    if (d < nN) {
        int beg = g_rowptr[d], end = g_rowptr[d + 1];
        float aldd = g_ald[d];
        float acc0 = 0.f, acc1 = 0.f, dn = 0.f;
        for (int base = beg; base < end; base += 32) {
            int cnt = min(32, end - base);
            int si = 0; float ex = 0.f;
            if (lane < cnt) {
                si = g_csr[base + lane];
                ex = __expf(lrelu(g_als[si] + aldd));
            }
            dn += ex;
            int j = 0;
            for (; j + 4 <= cnt; j += 4) {
                int s0 = __shfl_sync(0xffffffffu, si, j);
                int s1 = __shfl_sync(0xffffffffu, si, j + 1);
                int s2 = __shfl_sync(0xffffffffu, si, j + 2);
                int s3 = __shfl_sync(0xffffffffu, si, j + 3);
                float w0 = __shfl_sync(0xffffffffu, ex, j);
                float w1 = __shfl_sync(0xffffffffu, ex, j + 1);
                float w2 = __shfl_sync(0xffffffffu, ex, j + 2);
                float w3 = __shfl_sync(0xffffffffu, ex, j + 3);
                float2 v0 = ldxh(s0, lane);
                float2 v1 = ldxh(s1, lane);
                float2 v2 = ldxh(s2, lane);
                float2 v3 = ldxh(s3, lane);
                acc0 += w0 * v0.x; acc1 += w0 * v0.y;
                acc0 += w1 * v1.x; acc1 += w1 * v1.y;
                acc0 += w2 * v2.x; acc1 += w2 * v2.y;
                acc0 += w3 * v3.x; acc1 += w3 * v3.y;
            }
            for (; j < cnt; j++) {
                int s0 = __shfl_sync(0xffffffffu, si, j);
                float w0 = __shfl_sync(0xffffffffu, ex, j);
                float2 v0 = ldxh(s0, lane);
                acc0 += w0 * v0.x; acc1 += w0 * v0.y;
            }
        }
        {
            float ex = __expf(lrelu(g_als[d] + aldd));
            if (lane == 0) dn += ex;
            float2 v = ldxh(d, lane);
            acc0 += ex * v.x; acc1 += ex * v.y;
        }
#pragma unroll
        for (int o = 16; o > 0; o >>= 1) dn += __shfl_xor_sync(0xffffffffu, dn, o);
        float rd = 1.f / (dn + 1e-16f);
        float o0 = acc0 * rd, o1 = acc1 * rd;
        *(float2*)&g_agg2[d * 64 + c2] = make_float2(o0, o1);
        atomicAdd(&ssum[c2], o0);     atomicAdd(&ssum[c2 + 1], o1);
        atomicAdd(&ssq[c2], o0 * o0); atomicAdd(&ssq[c2 + 1], o1 * o1);
    }
    __syncthreads();
    if (tid < 64) {
        atomicAdd(&g_bnsum[tid], ssum[tid]);
        atomicAdd(&g_bnsq[tid], ssq[tid]);
    }
}

// ---------------- BN finalize (+ re-zero stats) ----------------
__global__ void k_bnfin(const float* __restrict__ gamma, const float* __restrict__ beta, int nN) {
    int c = threadIdx.x;
    if (c >= 64) return;
    float inv = 1.f / (float)nN;
    float mu = g_bnsum[c] * inv;
    float var = g_bnsq[c] * inv - mu * mu;
    float rs = rsqrtf(fmaxf(var, 0.f) + 1e-5f);
    float sc = gamma[c] * rs;
    g_scale[c] = sc;
    g_shift[c] = beta[c] - mu * sc;
    g_bnsum[c] = 0.f;
    g_bnsq[c] = 0.f;
}

// ---------------- pooling: privatized per 64-node chunk (batch is sorted) ----------------
__global__ __launch_bounds__(256) void k_pool(const int* __restrict__ batch, int nN) {
    __shared__ float ssum[256];
    __shared__ float smax[256];
    int tid = threadIdx.x;
    int n0 = blockIdx.x * PNODES;
    if (n0 >= nN) return;
    int nEnd = min(n0 + PNODES, nN);
    int c = tid & 63, r = tid >> 6;
    int g0 = batch[n0];
    int g1 = batch[nEnd - 1];
    if (g0 == g1) {
        float sc = g_scale[c], sh = g_shift[c];
        float s = 0.f, m = -3.4e38f;
        for (int n = n0 + r; n < nEnd; n += 4) {
            float y = eluf(sc * g_agg2[n * 64 + c] + sh);
            s += y; m = fmaxf(m, y);
        }
        ssum[tid] = s; smax[tid] = m;
        __syncthreads();
        if (r == 0) {
            s = ssum[c] + ssum[64 + c] + ssum[128 + c] + ssum[192 + c];
            m = fmaxf(fmaxf(smax[c], smax[64 + c]), fmaxf(smax[128 + c], smax[192 + c]));
            atomicAdd(&g_psum[g0 * 64 + c], s);
            atomicMax(&g_pmax[g0 * 64 + c], fenc(m));
            if (c == 0) atomicAdd(&g_cnt[g0], (float)(nEnd - n0));
        }
    } else {
        int tot = (nEnd - n0) * 64;
        for (int i = tid; i < tot; i += 256) {
            int n = n0 + (i >> 6);
            int cc = i & 63;
            int g = batch[n];
            float y = eluf(g_scale[cc] * g_agg2[n * 64 + cc] + g_shift[cc]);
            atomicAdd(&g_psum[g * 64 + cc], y);
            atomicMax(&g_pmax[g * 64 + cc], fenc(y));
            if (cc == 0) atomicAdd(&g_cnt[g], 1.f);
        }
    }
}

// ---------------- final projection ----------------
__global__ __launch_bounds__(128) void k_final(const float* __restrict__ Wout,
                                               const float* __restrict__ bout,
                                               float* __restrict__ out) {
    __shared__ float comb[128];
    int g = blockIdx.x, c = threadIdx.x;
    float cnt = g_cnt[g];
    if (c < 64) {
        comb[c] = (cnt > 0.f) ? fdec(g_pmax[g * 64 + c]) : 0.f;
    } else {
        comb[c] = g_psum[g * 64 + (c - 64)] / fmaxf(cnt, 1.f);
    }
    __syncthreads();
    float acc = bout[c];
#pragma unroll 16
    for (int k = 0; k < 128; k++) acc += comb[k] * Wout[k * 128 + c];
    out[g * 128 + c] = acc;
}

// ---------------- launcher: fork/join — node1 overlaps CSR build ----------------
extern "C" void kernel_launch(void* const* d_in, const int* in_sizes, int n_in,
                              void* d_out, int out_size) {
    const float* x     = (const float*)d_in[0];
    const int*   ei    = (const int*)d_in[1];
    const int*   batch = (const int*)d_in[2];
    const float* Wemb  = (const float*)d_in[3];
    const float* bemb  = (const float*)d_in[4];
    const float* W1    = (const float*)d_in[5];
    const float* a1s   = (const float*)d_in[6];
    const float* a1d   = (const float*)d_in[7];
    // d_in[8] = b1 (cancels in BN)
    const float* g1    = (const float*)d_in[9];
    const float* be1   = (const float*)d_in[10];
    const float* W2    = (const float*)d_in[11];
    const float* a2s   = (const float*)d_in[12];
    const float* a2d   = (const float*)d_in[13];
    // d_in[14] = b2 (cancels in BN)
    const float* g2    = (const float*)d_in[15];
    const float* be2   = (const float*)d_in[16];
    const float* Wout  = (const float*)d_in[17];
    const float* bout  = (const float*)d_in[18];
    float* out = (float*)d_out;

    int nN = in_sizes[2];
    int E  = in_sizes[1] / 2;
    const int* src = ei;
    const int* dst = ei + E;

    // side stream + events (created fresh each call; never destroyed — destroying
    // a stream that is part of an active capture would invalidate the capture.
    // No device memory is allocated by these objects.)
    cudaStream_t s1;
    cudaEvent_t e0, e1;
    cudaStreamCreateWithFlags(&s1, cudaStreamNonBlocking);
    cudaEventCreateWithFlags(&e0, cudaEventDisableTiming);
    cudaEventCreateWithFlags(&e1, cudaEventDisableTiming);

    // fork: node1 (inputs only) runs concurrently with init + CSR build
    cudaEventRecord(e0, 0);
    cudaStreamWaitEvent(s1, e0, 0);
    k_node1<<<(nN + 31) / 32, 256, 0, s1>>>(x, Wemb, bemb, W1, a1s, a1d, nN);
    cudaEventRecord(e1, s1);

    // main stream: init + CSR by dst
    k_init<<<1024, 256>>>();
    k_hist<<<(E + 255) / 256, 256>>>(dst, E);
    int nb = (nN + SCAN_B - 1) / SCAN_B;
    k_scan_a<<<nb, SCAN_B>>>(nN);
    k_scan_b<<<1, 128>>>(nb);
    k_scan_c<<<(nN + 255) / 256, 256>>>(nN);
    k_fill<<<(E + 255) / 256, 256>>>(src, dst, E);

    // join: gat1 needs CSR (main) + node1 outputs (s1)
    cudaStreamWaitEvent(0, e1, 0);

    // ---- conv1 (heads=2, out=32) ----
    k_gat1<<<(nN * 32 + 255) / 256, 256>>>(nN);
    k_bnfin<<<1, 64>>>(g1, be1, nN);

    // ---- conv2 (heads=1, out=64) ----
    k_node2<<<(nN + 31) / 32, 256>>>(W2, a2s, a2d, nN);
    k_gat2<<<(nN * 32 + 255) / 256, 256>>>(nN);
    k_bnfin<<<1, 64>>>(g2, be2, nN);

    // ---- pool + projection ----
    k_pool<<<(nN + PNODES - 1) / PNODES, 256>>>(batch, nN);
    k_final<<<NG, 128>>>(Wout, bout, out);
}